// round 13
// baseline (speedup 1.0000x reference)
#include <cuda_runtime.h>
#include <cuda_bf16.h>
#include <cuda_fp16.h>
#include <math.h>
#include <stdint.h>

// Problem constants (fixed by setup_inputs)
#define NN      50000
#define EE      800000
#define F_IN    128
#define WID     128
#define F_OUT   64
#define KK      128          // inner dim is 128 for every layer

#define SCAN_B  1024
#define SCAN_NB ((NN + SCAN_B - 1) / SCAN_B)   // 49

// ---------------- device scratch (no allocation allowed) ----------------
__device__ __align__(16) __half g_Ahi[NN * KK];     // split activations (GEMM input)
__device__ __align__(16) __half g_Alo[NN * KK];
__device__ float g_abc[NN * (3 * WID)];             // GEMM output: a | d (2*WID used)
__device__ __align__(16) __half g_Wthi0[3 * WID * KK];  // pre-split transposed weights [Ncol][K]
__device__ __align__(16) __half g_Wtlo0[3 * WID * KK];
__device__ __align__(16) __half g_Wthi1[3 * WID * KK];
__device__ __align__(16) __half g_Wtlo1[3 * WID * KK];
__device__ __align__(16) __half g_Wthi2[3 * F_OUT * KK];
__device__ __align__(16) __half g_Wtlo2[3 * F_OUT * KK];
__device__ float g_bcat0[3 * WID];
__device__ float g_bcat1[3 * WID];
__device__ float g_bcat2[3 * F_OUT];
__device__ float g_s[NN];
__device__ int   g_deg[NN];
__device__ int   g_rowptr[NN + 1];
__device__ int   g_cursor[NN];
__device__ int   g_bsum[SCAN_NB];
__device__ int   g_src[EE];
__device__ float g_ew[EE];
__device__ int   g_is64;

__device__ __forceinline__ int edge_idx(const void* ei, int idx) {
    if (g_is64) return (int)((const long long*)ei)[idx];
    return ((const int*)ei)[idx];
}

__device__ __forceinline__ void split1(float v, __half& hi, __half& lo) {
    hi = __float2half_rn(v);
    lo = __float2half_rn(v - __half2float(hi));
}

// L2-only (bypass L1) float4 load for the random gather
__device__ __forceinline__ float4 ldcg_f4(const float* p) {
    float4 v;
    asm volatile("ld.global.cg.v4.f32 {%0,%1,%2,%3}, [%4];"
                 : "=f"(v.x), "=f"(v.y), "=f"(v.z), "=f"(v.w) : "l"(p));
    return v;
}
__device__ __forceinline__ float2 ldcg_f2(const float* p) {
    float2 v;
    asm volatile("ld.global.cg.v2.f32 {%0,%1}, [%2];"
                 : "=f"(v.x), "=f"(v.y) : "l"(p));
    return v;
}

// ---------------- preprocessing ----------------
__global__ void zero_kernel(const int* __restrict__ ei_raw) {
    int i = blockIdx.x * blockDim.x + threadIdx.x;
    if (i < NN) { g_deg[i] = 0; g_s[i] = 0.f; }
    if (blockIdx.x == 0 && threadIdx.x == 0) {
        int is64 = 1;
        for (int t = 0; t < 64; t++)
            if (ei_raw[2 * t + 1] != 0) { is64 = 0; break; }
        g_is64 = is64;
    }
}

// split x into fp16 hi/lo (one shot, layer-0 input)
__global__ void convert_x_kernel(const float4* __restrict__ x4, int n4) {
    int i = blockIdx.x * blockDim.x + threadIdx.x;
    if (i >= n4) return;
    float4 v = x4[i];
    __half2 h01 = __float22half2_rn(make_float2(v.x, v.y));
    __half2 h23 = __float22half2_rn(make_float2(v.z, v.w));
    float2 f01 = __half22float2(h01);
    float2 f23 = __half22float2(h23);
    __half2 l01 = __float22half2_rn(make_float2(v.x - f01.x, v.y - f01.y));
    __half2 l23 = __float22half2_rn(make_float2(v.z - f23.x, v.w - f23.y));
    uint2 uh = make_uint2(*reinterpret_cast<uint32_t*>(&h01), *reinterpret_cast<uint32_t*>(&h23));
    uint2 ul = make_uint2(*reinterpret_cast<uint32_t*>(&l01), *reinterpret_cast<uint32_t*>(&l23));
    *reinterpret_cast<uint2*>(g_Ahi + (size_t)i * 4) = uh;
    *reinterpret_cast<uint2*>(g_Alo + (size_t)i * 4) = ul;
}

__global__ void hist_kernel(const void* __restrict__ ei,
                            const float* __restrict__ ea) {
    int e = blockIdx.x * blockDim.x + threadIdx.x;
    if (e < EE) {
        int dst = edge_idx(ei, EE + e);
        if ((unsigned)dst >= NN) return;
        atomicAdd(&g_deg[dst], 1);
        atomicAdd(&g_s[dst], ea[e]);
    }
}

__global__ __launch_bounds__(SCAN_B) void scan1_kernel() {
    __shared__ int wsum[32];
    int i = blockIdx.x * SCAN_B + threadIdx.x;
    int lane = threadIdx.x & 31;
    int wid  = threadIdx.x >> 5;
    int v = (i < NN) ? g_deg[i] : 0;
    int incl = v;
    #pragma unroll
    for (int off = 1; off < 32; off <<= 1) {
        int t = __shfl_up_sync(0xffffffffu, incl, off);
        if (lane >= off) incl += t;
    }
    if (lane == 31) wsum[wid] = incl;
    __syncthreads();
    if (wid == 0) {
        int s = wsum[lane];
        #pragma unroll
        for (int off = 1; off < 32; off <<= 1) {
            int t = __shfl_up_sync(0xffffffffu, s, off);
            if (lane >= off) s += t;
        }
        wsum[lane] = s;
    }
    __syncthreads();
    if (wid > 0) incl += wsum[wid - 1];
    if (i < NN) g_rowptr[i + 1] = incl;
    if (threadIdx.x == SCAN_B - 1) g_bsum[blockIdx.x] = incl;
}

// scan3: apply per-block carry computed locally from g_bsum (no separate scan2 launch)
__global__ __launch_bounds__(SCAN_B) void scan3_kernel() {
    __shared__ int boff_s;
    if (threadIdx.x == 0) {
        int run = 0;
        for (int b = 0; b < blockIdx.x; b++) run += g_bsum[b];
        boff_s = run;
    }
    __syncthreads();
    int i = blockIdx.x * SCAN_B + threadIdx.x;
    if (i < NN) {
        int rp = g_rowptr[i + 1] + boff_s;
        g_rowptr[i + 1] = rp;
        g_cursor[i] = rp - g_deg[i];
    }
    if (i == 0) g_rowptr[0] = 0;
}

__global__ void scatter_kernel(const void* __restrict__ ei,
                               const float* __restrict__ ea) {
    int e = blockIdx.x * blockDim.x + threadIdx.x;
    if (e < EE) {
        int src = edge_idx(ei, e);
        int dst = edge_idx(ei, EE + e);
        if ((unsigned)src >= NN || (unsigned)dst >= NN) return;
        int pos = atomicAdd(&g_cursor[dst], 1);
        g_src[pos] = src;
        g_ew[pos]  = ea[e];
    }
}

// ------- weight packing: transposed + pre-split. Wt[col][k], col map: [W1 | interleave(W2,W3)] -------
__global__ void pack_w_kernel(const float* __restrict__ W1, const float* __restrict__ b1,
                              const float* __restrict__ W2,
                              const float* __restrict__ W3, const float* __restrict__ b3,
                              int K, int C,
                              __half* __restrict__ Wthi, __half* __restrict__ Wtlo,
                              float* __restrict__ bcat) {
    int i = blockIdx.x * blockDim.x + threadIdx.x;
    int total = K * C;
    if (i < total) {
        int k = i / C, c = i % C;
        __half h, l;
        split1(W1[i], h, l);
        Wthi[(size_t)c * KK + k] = h;               Wtlo[(size_t)c * KK + k] = l;
        split1(W2[i], h, l);
        Wthi[(size_t)(C + 2 * c) * KK + k] = h;     Wtlo[(size_t)(C + 2 * c) * KK + k] = l;
        split1(W3[i], h, l);
        Wthi[(size_t)(C + 2 * c + 1) * KK + k] = h; Wtlo[(size_t)(C + 2 * c + 1) * KK + k] = l;
    }
    if (i < C) {
        bcat[i]             = b1[i];
        bcat[C + 2 * i]     = 0.f;
        bcat[C + 2 * i + 1] = b3[i];
    }
}

// ========== tensor-core GEMM (3xFP16, pre-split operands) + fused LEConv epilogue ==========
// a-part (fp32, with b1 bias) and d-part (fp32) both into out [M x 2*AC]: [a(0:AC) | d(AC:2AC)]
#define AH_S 20                     // u32 per A-row per stage (16 data + 4 pad)
#define BH_S 68                     // u32 per B-row full-K (64 data + 4 pad)
#define OFF_ALO (2 * 128 * AH_S)    // 5120 u32
#define OFF_BHI (2 * OFF_ALO)       // 10240
#define OFF_BLO (OFF_BHI + 128 * BH_S)   // 18944
#define TG_SMEM ((OFF_BLO + 128 * BH_S) * 4)  // 110592 bytes

#define MMA_F16(d, a0, a1, a2, a3, b0, b1)                                              \
    asm volatile("mma.sync.aligned.m16n8k16.row.col.f32.f16.f16.f32 "                    \
                 "{%0,%1,%2,%3},{%4,%5,%6,%7},{%8,%9},{%0,%1,%2,%3};"                    \
                 : "+f"(d[0]), "+f"(d[1]), "+f"(d[2]), "+f"(d[3])                        \
                 : "r"(a0), "r"(a1), "r"(a2), "r"(a3), "r"(b0), "r"(b1))

__global__ __launch_bounds__(256, 1) void tgemm_kernel(const __half* __restrict__ Ahi,
                                                       const __half* __restrict__ Alo,
                                                       const __half* __restrict__ Wthi,
                                                       const __half* __restrict__ Wtlo,
                                                       const float* __restrict__ bias,
                                                       const float* __restrict__ svec,
                                                       int M, int AC,
                                                       float* __restrict__ out) {
    extern __shared__ uint32_t smu[];

    const int Ncol = 3 * AC;
    const int OS   = 2 * AC;
    const int tid = threadIdx.x;
    const int lane = tid & 31;
    const int g  = lane >> 2;
    const int tq = lane & 3;
    const int warp = tid >> 5;
    const int wm = warp & 1;
    const int wn = warp >> 1;
    const int row0 = blockIdx.x * 128;
    const int col0 = blockIdx.y * 128;

    const uint32_t sb = (uint32_t)__cvta_generic_to_shared(smu);

    auto load_a = [&](int s, int buf) {
        #pragma unroll
        for (int p = 0; p < 2; p++) {
            int f = tid + p * 256;
            int row = f >> 2, c = f & 3;
            bool valid = (row0 + row) < M;
            size_t gof = (valid ? (size_t)(row0 + row) : 0) * KK + s * 32 + c * 8;
            int bytes = valid ? 16 : 0;
            uint32_t du = (uint32_t)(buf * 128 * AH_S + row * AH_S + c * 4);
            asm volatile("cp.async.ca.shared.global [%0], [%1], 16, %2;"
                         :: "r"(sb + du * 4), "l"(Ahi + gof), "r"(bytes));
            asm volatile("cp.async.ca.shared.global [%0], [%1], 16, %2;"
                         :: "r"(sb + (OFF_ALO + du) * 4), "l"(Alo + gof), "r"(bytes));
        }
        asm volatile("cp.async.commit_group;");
    };

    auto load_b = [&]() {
        #pragma unroll
        for (int p = 0; p < 8; p++) {
            int f = tid + p * 256;
            int n = f >> 4, c = f & 15;
            bool valid = (col0 + n) < Ncol;
            size_t gof = (valid ? (size_t)(col0 + n) : 0) * KK + c * 8;
            int bytes = valid ? 16 : 0;
            uint32_t du = (uint32_t)(n * BH_S + c * 4);
            asm volatile("cp.async.ca.shared.global [%0], [%1], 16, %2;"
                         :: "r"(sb + (OFF_BHI + du) * 4), "l"(Wthi + gof), "r"(bytes));
            asm volatile("cp.async.ca.shared.global [%0], [%1], 16, %2;"
                         :: "r"(sb + (OFF_BLO + du) * 4), "l"(Wtlo + gof), "r"(bytes));
        }
        asm volatile("cp.async.commit_group;");
    };

    load_a(0, 0);
    load_b();
    load_a(1, 1);
    asm volatile("cp.async.wait_group 1;");
    __syncthreads();

    float acc[4][4][4];
    #pragma unroll
    for (int i = 0; i < 4; i++)
        #pragma unroll
        for (int j = 0; j < 4; j++)
            #pragma unroll
            for (int q = 0; q < 4; q++) acc[i][j][q] = 0.f;

    #pragma unroll
    for (int t = 0; t < 4; t++) {
        const uint32_t* ah = smu + (t & 1) * (128 * AH_S);
        const uint32_t* al = ah + OFF_ALO;

        #pragma unroll
        for (int kk = 0; kk < 2; kk++) {
            uint32_t ahi[4][4], alo[4][4];
            #pragma unroll
            for (int i = 0; i < 4; i++) {
                int r0 = wm * 64 + i * 16 + g;
                int b0i = r0 * AH_S + kk * 8 + tq;
                int b1i = (r0 + 8) * AH_S + kk * 8 + tq;
                ahi[i][0] = ah[b0i];     ahi[i][1] = ah[b1i];
                ahi[i][2] = ah[b0i + 4]; ahi[i][3] = ah[b1i + 4];
                alo[i][0] = al[b0i];     alo[i][1] = al[b1i];
                alo[i][2] = al[b0i + 4]; alo[i][3] = al[b1i + 4];
            }
            uint32_t bhi[4][2], blo[4][2];
            int k16 = t * 2 + kk;
            #pragma unroll
            for (int j = 0; j < 4; j++) {
                int nn = wn * 32 + j * 8 + g;
                int bi = nn * BH_S + k16 * 8 + tq;
                bhi[j][0] = smu[OFF_BHI + bi]; bhi[j][1] = smu[OFF_BHI + bi + 4];
                blo[j][0] = smu[OFF_BLO + bi]; blo[j][1] = smu[OFF_BLO + bi + 4];
            }
            #pragma unroll
            for (int i = 0; i < 4; i++)
                #pragma unroll
                for (int j = 0; j < 4; j++) {
                    MMA_F16(acc[i][j], ahi[i][0], ahi[i][1], ahi[i][2], ahi[i][3], bhi[j][0], bhi[j][1]);
                    MMA_F16(acc[i][j], ahi[i][0], ahi[i][1], ahi[i][2], ahi[i][3], blo[j][0], blo[j][1]);
                    MMA_F16(acc[i][j], alo[i][0], alo[i][1], alo[i][2], alo[i][3], bhi[j][0], bhi[j][1]);
                }
        }

        if (t < 3) {
            __syncthreads();
            if (t + 2 < 4) load_a(t + 2, t & 1);
            asm volatile("cp.async.wait_group %0;" :: "n"(1));
            if (t == 2) asm volatile("cp.async.wait_group 0;");
            __syncthreads();
        }
    }

    // ---- fused epilogue: a-part -> fp32 + b1 bias; (b,c) pair -> d = (c + b3) - s*b ----
    #pragma unroll
    for (int i = 0; i < 4; i++) {
        int gm0 = row0 + wm * 64 + i * 16 + g;
        int gm1 = gm0 + 8;
        float s0 = (gm0 < M) ? svec[gm0] : 0.f;
        float s1 = (gm1 < M) ? svec[gm1] : 0.f;
        #pragma unroll
        for (int j = 0; j < 4; j++) {
            int gn = col0 + wn * 32 + j * 8 + 2 * tq;
            if (gn >= Ncol) continue;
            if (gn < AC) {
                float2 bb = *reinterpret_cast<const float2*>(bias + gn);
                if (gm0 < M) {
                    float2 v0 = make_float2(acc[i][j][0] + bb.x, acc[i][j][1] + bb.y);
                    *reinterpret_cast<float2*>(out + (size_t)gm0 * OS + gn) = v0;
                }
                if (gm1 < M) {
                    float2 v1 = make_float2(acc[i][j][2] + bb.x, acc[i][j][3] + bb.y);
                    *reinterpret_cast<float2*>(out + (size_t)gm1 * OS + gn) = v1;
                }
            } else {
                int u = (gn - AC) >> 1;
                float b3v = bias[gn + 1];
                if (gm0 < M)
                    out[(size_t)gm0 * OS + AC + u] = (acc[i][j][1] + b3v) - s0 * acc[i][j][0];
                if (gm1 < M)
                    out[(size_t)gm1 * OS + AC + u] = (acc[i][j][3] + b3v) - s1 * acc[i][j][2];
            }
        }
    }
}

// ---------------- SpMM F=128: fp32 .cg gather, writes next layer's split fp16 activations ----------------
__global__ __launch_bounds__(256) void spmm128_kernel(const float* __restrict__ ad,
                                                      __half* __restrict__ hhi,
                                                      __half* __restrict__ hlo) {
    const int F = 128;
    const int stride = 2 * F;
    int w = blockIdx.x * 8 + (threadIdx.x >> 5);
    if (w >= NN) return;
    int lane = threadIdx.x & 31;
    int fbase = lane * 4;

    float4 acc = make_float4(0.f, 0.f, 0.f, 0.f);
    int beg = g_rowptr[w], end = g_rowptr[w + 1];
    int e = beg;
    for (; e + 3 < end; e += 4) {
        int   s0 = g_src[e],   s1 = g_src[e+1], s2 = g_src[e+2], s3 = g_src[e+3];
        float w0 = g_ew[e],    w1 = g_ew[e+1],  w2 = g_ew[e+2],  w3 = g_ew[e+3];
        float4 a0 = ldcg_f4(ad + (size_t)s0 * stride + fbase);
        float4 a1 = ldcg_f4(ad + (size_t)s1 * stride + fbase);
        float4 a2 = ldcg_f4(ad + (size_t)s2 * stride + fbase);
        float4 a3 = ldcg_f4(ad + (size_t)s3 * stride + fbase);
        acc.x += w0 * a0.x + w1 * a1.x + w2 * a2.x + w3 * a3.x;
        acc.y += w0 * a0.y + w1 * a1.y + w2 * a2.y + w3 * a3.y;
        acc.z += w0 * a0.z + w1 * a1.z + w2 * a2.z + w3 * a3.z;
        acc.w += w0 * a0.w + w1 * a1.w + w2 * a2.w + w3 * a3.w;
    }
    for (; e < end; e++) {
        int   s0 = g_src[e];
        float w0 = g_ew[e];
        float4 a0 = ldcg_f4(ad + (size_t)s0 * stride + fbase);
        acc.x += w0 * a0.x; acc.y += w0 * a0.y; acc.z += w0 * a0.z; acc.w += w0 * a0.w;
    }
    float4 dv = *reinterpret_cast<const float4*>(ad + (size_t)w * stride + F + fbase);
    float v[4];
    v[0] = acc.x + dv.x;
    v[1] = acc.y + dv.y;
    v[2] = acc.z + dv.z;
    v[3] = acc.w + dv.w;
    #pragma unroll
    for (int i = 0; i < 4; i++)
        v[i] = v[i] > 0.f ? v[i] : 0.1f * v[i];

    __half2 h01 = __float22half2_rn(make_float2(v[0], v[1]));
    __half2 h23 = __float22half2_rn(make_float2(v[2], v[3]));
    float2 f01 = __half22float2(h01);
    float2 f23 = __half22float2(h23);
    __half2 l01 = __float22half2_rn(make_float2(v[0] - f01.x, v[1] - f01.y));
    __half2 l23 = __float22half2_rn(make_float2(v[2] - f23.x, v[3] - f23.y));
    uint2 uh = make_uint2(*reinterpret_cast<uint32_t*>(&h01), *reinterpret_cast<uint32_t*>(&h23));
    uint2 ul = make_uint2(*reinterpret_cast<uint32_t*>(&l01), *reinterpret_cast<uint32_t*>(&l23));
    *reinterpret_cast<uint2*>(hhi + (size_t)w * F + fbase) = uh;
    *reinterpret_cast<uint2*>(hlo + (size_t)w * F + fbase) = ul;
}

// ---------------- SpMM F=64 (final layer): fp32 .cg gather, fp32 out, lrelu+sigmoid ----------------
__global__ __launch_bounds__(256) void spmm64_kernel(const float* __restrict__ ad,
                                                     float* __restrict__ out) {
    const int F = 64;
    const int stride = 2 * F;
    int w = blockIdx.x * 8 + (threadIdx.x >> 5);
    if (w >= NN) return;
    int lane = threadIdx.x & 31;
    int fbase = lane * 2;

    float2 acc = make_float2(0.f, 0.f);
    int beg = g_rowptr[w], end = g_rowptr[w + 1];
    int e = beg;
    for (; e + 3 < end; e += 4) {
        int   s0 = g_src[e],   s1 = g_src[e+1], s2 = g_src[e+2], s3 = g_src[e+3];
        float w0 = g_ew[e],    w1 = g_ew[e+1],  w2 = g_ew[e+2],  w3 = g_ew[e+3];
        float2 a0 = ldcg_f2(ad + (size_t)s0 * stride + fbase);
        float2 a1 = ldcg_f2(ad + (size_t)s1 * stride + fbase);
        float2 a2 = ldcg_f2(ad + (size_t)s2 * stride + fbase);
        float2 a3 = ldcg_f2(ad + (size_t)s3 * stride + fbase);
        acc.x += w0 * a0.x + w1 * a1.x + w2 * a2.x + w3 * a3.x;
        acc.y += w0 * a0.y + w1 * a1.y + w2 * a2.y + w3 * a3.y;
    }
    for (; e < end; e++) {
        int   s0 = g_src[e];
        float w0 = g_ew[e];
        float2 a0 = ldcg_f2(ad + (size_t)s0 * stride + fbase);
        acc.x += w0 * a0.x; acc.y += w0 * a0.y;
    }
    float2 dv = *reinterpret_cast<const float2*>(ad + (size_t)w * stride + F + fbase);
    float v[2];
    v[0] = acc.x + dv.x;
    v[1] = acc.y + dv.y;
    #pragma unroll
    for (int i = 0; i < 2; i++) {
        float t = v[i] > 0.f ? v[i] : 0.1f * v[i];
        v[i] = 1.f / (1.f + expf(-t));
    }
    *reinterpret_cast<float2*>(out + (size_t)w * F + fbase) = make_float2(v[0], v[1]);
}

// ---------------- host launch ----------------
extern "C" void kernel_launch(void* const* d_in, const int* in_sizes, int n_in,
                              void* d_out, int out_size) {
    const float* x  = (const float*)d_in[0];
    const void*  ei = d_in[1];
    const float* ea = (const float*)d_in[2];
    const float* W1_in  = (const float*)d_in[4];
    const float* b1_in  = (const float*)d_in[5];
    const float* W2_in  = (const float*)d_in[6];
    const float* W3_in  = (const float*)d_in[7];
    const float* b3_in  = (const float*)d_in[8];
    const float* W1_mid = (const float*)d_in[9];
    const float* b1_mid = (const float*)d_in[10];
    const float* W2_mid = (const float*)d_in[11];
    const float* W3_mid = (const float*)d_in[12];
    const float* b3_mid = (const float*)d_in[13];
    const float* W1_out = (const float*)d_in[14];
    const float* b1_out = (const float*)d_in[15];
    const float* W2_out = (const float*)d_in[16];
    const float* W3_out = (const float*)d_in[17];
    const float* b3_out = (const float*)d_in[18];

    float* out = (float*)d_out;

    float *d_abc, *d_b0, *d_b1, *d_b2, *d_s;
    __half *d_Ahi, *d_Alo, *d_Wh0, *d_Wl0, *d_Wh1, *d_Wl1, *d_Wh2, *d_Wl2;
    cudaGetSymbolAddress((void**)&d_abc, g_abc);
    cudaGetSymbolAddress((void**)&d_Ahi, g_Ahi);
    cudaGetSymbolAddress((void**)&d_Alo, g_Alo);
    cudaGetSymbolAddress((void**)&d_Wh0, g_Wthi0);
    cudaGetSymbolAddress((void**)&d_Wl0, g_Wtlo0);
    cudaGetSymbolAddress((void**)&d_Wh1, g_Wthi1);
    cudaGetSymbolAddress((void**)&d_Wl1, g_Wtlo1);
    cudaGetSymbolAddress((void**)&d_Wh2, g_Wthi2);
    cudaGetSymbolAddress((void**)&d_Wl2, g_Wtlo2);
    cudaGetSymbolAddress((void**)&d_b0,  g_bcat0);
    cudaGetSymbolAddress((void**)&d_b1,  g_bcat1);
    cudaGetSymbolAddress((void**)&d_b2,  g_bcat2);
    cudaGetSymbolAddress((void**)&d_s,   g_s);

    cudaFuncSetAttribute(tgemm_kernel, cudaFuncAttributeMaxDynamicSharedMemorySize, TG_SMEM);

    // --- pack weights (pre-split, transposed) + split x ---
    pack_w_kernel<<<(F_IN * WID + 255) / 256, 256>>>(W1_in,  b1_in,  W2_in,  W3_in,  b3_in,  F_IN, WID,   d_Wh0, d_Wl0, d_b0);
    pack_w_kernel<<<(WID * WID + 255) / 256, 256>>>(W1_mid, b1_mid, W2_mid, W3_mid, b3_mid, WID,  WID,   d_Wh1, d_Wl1, d_b1);
    pack_w_kernel<<<(WID * F_OUT + 255) / 256, 256>>>(W1_out, b1_out, W2_out, W3_out, b3_out, WID, F_OUT, d_Wh2, d_Wl2, d_b2);
    convert_x_kernel<<<(NN * KK / 4 + 255) / 256, 256>>>((const float4*)x, NN * KK / 4);

    // --- preprocessing: zero+detect, s[i], CSR ---
    zero_kernel<<<(NN + 255) / 256, 256>>>((const int*)ei);
    hist_kernel<<<(EE + 255) / 256, 256>>>(ei, ea);
    scan1_kernel<<<SCAN_NB, SCAN_B>>>();
    scan3_kernel<<<SCAN_NB, SCAN_B>>>();
    scatter_kernel<<<(EE + 255) / 256, 256>>>(ei, ea);

    const int spmm_blocks = (NN + 7) / 8;
    const int grid_m = (NN + 127) / 128;

    // --- layer 0 (in) ---
    {
        dim3 grid(grid_m, (3 * WID + 127) / 128);
        tgemm_kernel<<<grid, 256, TG_SMEM>>>(d_Ahi, d_Alo, d_Wh0, d_Wl0, d_b0, d_s, NN, WID, d_abc);
        spmm128_kernel<<<spmm_blocks, 256>>>(d_abc, d_Ahi, d_Alo);
    }

    // --- layers 1,2 (mid) ---
    for (int l = 0; l < 2; l++) {
        dim3 grid(grid_m, (3 * WID + 127) / 128);
        tgemm_kernel<<<grid, 256, TG_SMEM>>>(d_Ahi, d_Alo, d_Wh1, d_Wl1, d_b1, d_s, NN, WID, d_abc);
        spmm128_kernel<<<spmm_blocks, 256>>>(d_abc, d_Ahi, d_Alo);
    }

    // --- layer 3 (out): lrelu+sigmoid, fp32 out ---
    {
        dim3 grid(grid_m, (3 * F_OUT + 127) / 128);
        tgemm_kernel<<<grid, 256, TG_SMEM>>>(d_Ahi, d_Alo, d_Wh2, d_Wl2, d_b2, d_s, NN, F_OUT, d_abc);
        spmm64_kernel<<<spmm_blocks, 256>>>(d_abc, out);
    }
}

// round 14
// speedup vs baseline: 1.0515x; 1.0515x over previous
#include <cuda_runtime.h>
#include <cuda_bf16.h>
#include <cuda_fp16.h>
#include <math.h>
#include <stdint.h>

// Problem constants (fixed by setup_inputs)
#define NN      50000
#define EE      800000
#define F_IN    128
#define WID     128
#define F_OUT   64
#define KK      128          // inner dim is 128 for every layer

#define SCAN_B  1024
#define SCAN_NB ((NN + SCAN_B - 1) / SCAN_B)   // 49

// ---------------- device scratch (no allocation allowed) ----------------
__device__ __align__(16) __half g_Ahi[NN * KK];     // split activations (GEMM input)
__device__ __align__(16) __half g_Alo[NN * KK];
__device__ float g_abc[NN * (3 * WID)];             // GEMM output: a | d (2*WID used)
__device__ __align__(16) __half g_Wthi0[3 * WID * KK];  // pre-split transposed weights [Ncol][K]
__device__ __align__(16) __half g_Wtlo0[3 * WID * KK];
__device__ __align__(16) __half g_Wthi1[3 * WID * KK];
__device__ __align__(16) __half g_Wtlo1[3 * WID * KK];
__device__ __align__(16) __half g_Wthi2[3 * F_OUT * KK];
__device__ __align__(16) __half g_Wtlo2[3 * F_OUT * KK];
__device__ float g_bcat0[3 * WID];
__device__ float g_bcat1[3 * WID];
__device__ float g_bcat2[3 * F_OUT];
__device__ float g_s[NN];
__device__ int   g_deg[NN];
__device__ int   g_rowptr[NN + 1];
__device__ int   g_cursor[NN];
__device__ int   g_bsum[SCAN_NB];
__device__ int   g_src[EE];
__device__ float g_ew[EE];
__device__ int   g_is64;

__device__ __forceinline__ int edge_idx(const void* ei, int idx) {
    if (g_is64) return (int)((const long long*)ei)[idx];
    return ((const int*)ei)[idx];
}

__device__ __forceinline__ void split1(float v, __half& hi, __half& lo) {
    hi = __float2half_rn(v);
    lo = __float2half_rn(v - __half2float(hi));
}

// ---------------- preprocessing ----------------
__global__ void zero_kernel(const int* __restrict__ ei_raw) {
    int i = blockIdx.x * blockDim.x + threadIdx.x;
    if (i < NN) { g_deg[i] = 0; g_s[i] = 0.f; }
    if (blockIdx.x == 0 && threadIdx.x == 0) {
        int is64 = 1;
        for (int t = 0; t < 64; t++)
            if (ei_raw[2 * t + 1] != 0) { is64 = 0; break; }
        g_is64 = is64;
    }
}

// split x into fp16 hi/lo (one shot, layer-0 input)
__global__ void convert_x_kernel(const float4* __restrict__ x4, int n4) {
    int i = blockIdx.x * blockDim.x + threadIdx.x;
    if (i >= n4) return;
    float4 v = x4[i];
    __half2 h01 = __float22half2_rn(make_float2(v.x, v.y));
    __half2 h23 = __float22half2_rn(make_float2(v.z, v.w));
    float2 f01 = __half22float2(h01);
    float2 f23 = __half22float2(h23);
    __half2 l01 = __float22half2_rn(make_float2(v.x - f01.x, v.y - f01.y));
    __half2 l23 = __float22half2_rn(make_float2(v.z - f23.x, v.w - f23.y));
    uint2 uh = make_uint2(*reinterpret_cast<uint32_t*>(&h01), *reinterpret_cast<uint32_t*>(&h23));
    uint2 ul = make_uint2(*reinterpret_cast<uint32_t*>(&l01), *reinterpret_cast<uint32_t*>(&l23));
    *reinterpret_cast<uint2*>(g_Ahi + (size_t)i * 4) = uh;
    *reinterpret_cast<uint2*>(g_Alo + (size_t)i * 4) = ul;
}

__global__ void hist_kernel(const void* __restrict__ ei,
                            const float* __restrict__ ea) {
    int e = blockIdx.x * blockDim.x + threadIdx.x;
    if (e < EE) {
        int dst = edge_idx(ei, EE + e);
        if ((unsigned)dst >= NN) return;
        atomicAdd(&g_deg[dst], 1);
        atomicAdd(&g_s[dst], ea[e]);
    }
}

__global__ __launch_bounds__(SCAN_B) void scan1_kernel() {
    __shared__ int wsum[32];
    int i = blockIdx.x * SCAN_B + threadIdx.x;
    int lane = threadIdx.x & 31;
    int wid  = threadIdx.x >> 5;
    int v = (i < NN) ? g_deg[i] : 0;
    int incl = v;
    #pragma unroll
    for (int off = 1; off < 32; off <<= 1) {
        int t = __shfl_up_sync(0xffffffffu, incl, off);
        if (lane >= off) incl += t;
    }
    if (lane == 31) wsum[wid] = incl;
    __syncthreads();
    if (wid == 0) {
        int s = wsum[lane];
        #pragma unroll
        for (int off = 1; off < 32; off <<= 1) {
            int t = __shfl_up_sync(0xffffffffu, s, off);
            if (lane >= off) s += t;
        }
        wsum[lane] = s;
    }
    __syncthreads();
    if (wid > 0) incl += wsum[wid - 1];
    if (i < NN) g_rowptr[i + 1] = incl;
    if (threadIdx.x == SCAN_B - 1) g_bsum[blockIdx.x] = incl;
}

// scan3: apply per-block carry computed locally from g_bsum (no separate scan2 launch)
__global__ __launch_bounds__(SCAN_B) void scan3_kernel() {
    __shared__ int boff_s;
    if (threadIdx.x == 0) {
        int run = 0;
        for (int b = 0; b < blockIdx.x; b++) run += g_bsum[b];
        boff_s = run;
    }
    __syncthreads();
    int i = blockIdx.x * SCAN_B + threadIdx.x;
    if (i < NN) {
        int rp = g_rowptr[i + 1] + boff_s;
        g_rowptr[i + 1] = rp;
        g_cursor[i] = rp - g_deg[i];
    }
    if (i == 0) g_rowptr[0] = 0;
}

__global__ void scatter_kernel(const void* __restrict__ ei,
                               const float* __restrict__ ea) {
    int e = blockIdx.x * blockDim.x + threadIdx.x;
    if (e < EE) {
        int src = edge_idx(ei, e);
        int dst = edge_idx(ei, EE + e);
        if ((unsigned)src >= NN || (unsigned)dst >= NN) return;
        int pos = atomicAdd(&g_cursor[dst], 1);
        g_src[pos] = src;
        g_ew[pos]  = ea[e];
    }
}

// ------- weight packing: transposed + pre-split. Wt[col][k], col map: [W1 | interleave(W2,W3)] -------
__global__ void pack_w_kernel(const float* __restrict__ W1, const float* __restrict__ b1,
                              const float* __restrict__ W2,
                              const float* __restrict__ W3, const float* __restrict__ b3,
                              int K, int C,
                              __half* __restrict__ Wthi, __half* __restrict__ Wtlo,
                              float* __restrict__ bcat) {
    int i = blockIdx.x * blockDim.x + threadIdx.x;
    int total = K * C;
    if (i < total) {
        int k = i / C, c = i % C;
        __half h, l;
        split1(W1[i], h, l);
        Wthi[(size_t)c * KK + k] = h;               Wtlo[(size_t)c * KK + k] = l;
        split1(W2[i], h, l);
        Wthi[(size_t)(C + 2 * c) * KK + k] = h;     Wtlo[(size_t)(C + 2 * c) * KK + k] = l;
        split1(W3[i], h, l);
        Wthi[(size_t)(C + 2 * c + 1) * KK + k] = h; Wtlo[(size_t)(C + 2 * c + 1) * KK + k] = l;
    }
    if (i < C) {
        bcat[i]             = b1[i];
        bcat[C + 2 * i]     = 0.f;
        bcat[C + 2 * i + 1] = b3[i];
    }
}

// ========== tensor-core GEMM (3xFP16, pre-split operands) + fused LEConv epilogue ==========
// a-part (fp32, with b1 bias) and d-part (fp32) both into out [M x 2*AC]: [a(0:AC) | d(AC:2AC)]
#define AH_S 20                     // u32 per A-row per stage (16 data + 4 pad)
#define BH_S 68                     // u32 per B-row full-K (64 data + 4 pad)
#define OFF_ALO (2 * 128 * AH_S)    // 5120 u32
#define OFF_BHI (2 * OFF_ALO)       // 10240
#define OFF_BLO (OFF_BHI + 128 * BH_S)   // 18944
#define TG_SMEM ((OFF_BLO + 128 * BH_S) * 4)  // 110592 bytes

#define MMA_F16(d, a0, a1, a2, a3, b0, b1)                                              \
    asm volatile("mma.sync.aligned.m16n8k16.row.col.f32.f16.f16.f32 "                    \
                 "{%0,%1,%2,%3},{%4,%5,%6,%7},{%8,%9},{%0,%1,%2,%3};"                    \
                 : "+f"(d[0]), "+f"(d[1]), "+f"(d[2]), "+f"(d[3])                        \
                 : "r"(a0), "r"(a1), "r"(a2), "r"(a3), "r"(b0), "r"(b1))

__global__ __launch_bounds__(256, 1) void tgemm_kernel(const __half* __restrict__ Ahi,
                                                       const __half* __restrict__ Alo,
                                                       const __half* __restrict__ Wthi,
                                                       const __half* __restrict__ Wtlo,
                                                       const float* __restrict__ bias,
                                                       const float* __restrict__ svec,
                                                       int M, int AC,
                                                       float* __restrict__ out) {
    extern __shared__ uint32_t smu[];

    const int Ncol = 3 * AC;
    const int OS   = 2 * AC;
    const int tid = threadIdx.x;
    const int lane = tid & 31;
    const int g  = lane >> 2;
    const int tq = lane & 3;
    const int warp = tid >> 5;
    const int wm = warp & 1;
    const int wn = warp >> 1;
    const int row0 = blockIdx.x * 128;
    const int col0 = blockIdx.y * 128;

    const uint32_t sb = (uint32_t)__cvta_generic_to_shared(smu);

    auto load_a = [&](int s, int buf) {
        #pragma unroll
        for (int p = 0; p < 2; p++) {
            int f = tid + p * 256;
            int row = f >> 2, c = f & 3;
            bool valid = (row0 + row) < M;
            size_t gof = (valid ? (size_t)(row0 + row) : 0) * KK + s * 32 + c * 8;
            int bytes = valid ? 16 : 0;
            uint32_t du = (uint32_t)(buf * 128 * AH_S + row * AH_S + c * 4);
            asm volatile("cp.async.ca.shared.global [%0], [%1], 16, %2;"
                         :: "r"(sb + du * 4), "l"(Ahi + gof), "r"(bytes));
            asm volatile("cp.async.ca.shared.global [%0], [%1], 16, %2;"
                         :: "r"(sb + (OFF_ALO + du) * 4), "l"(Alo + gof), "r"(bytes));
        }
        asm volatile("cp.async.commit_group;");
    };

    auto load_b = [&]() {
        #pragma unroll
        for (int p = 0; p < 8; p++) {
            int f = tid + p * 256;
            int n = f >> 4, c = f & 15;
            bool valid = (col0 + n) < Ncol;
            size_t gof = (valid ? (size_t)(col0 + n) : 0) * KK + c * 8;
            int bytes = valid ? 16 : 0;
            uint32_t du = (uint32_t)(n * BH_S + c * 4);
            asm volatile("cp.async.ca.shared.global [%0], [%1], 16, %2;"
                         :: "r"(sb + (OFF_BHI + du) * 4), "l"(Wthi + gof), "r"(bytes));
            asm volatile("cp.async.ca.shared.global [%0], [%1], 16, %2;"
                         :: "r"(sb + (OFF_BLO + du) * 4), "l"(Wtlo + gof), "r"(bytes));
        }
        asm volatile("cp.async.commit_group;");
    };

    load_a(0, 0);
    load_b();
    load_a(1, 1);
    asm volatile("cp.async.wait_group 1;");
    __syncthreads();

    float acc[4][4][4];
    #pragma unroll
    for (int i = 0; i < 4; i++)
        #pragma unroll
        for (int j = 0; j < 4; j++)
            #pragma unroll
            for (int q = 0; q < 4; q++) acc[i][j][q] = 0.f;

    #pragma unroll
    for (int t = 0; t < 4; t++) {
        const uint32_t* ah = smu + (t & 1) * (128 * AH_S);
        const uint32_t* al = ah + OFF_ALO;

        #pragma unroll
        for (int kk = 0; kk < 2; kk++) {
            uint32_t ahi[4][4], alo[4][4];
            #pragma unroll
            for (int i = 0; i < 4; i++) {
                int r0 = wm * 64 + i * 16 + g;
                int b0i = r0 * AH_S + kk * 8 + tq;
                int b1i = (r0 + 8) * AH_S + kk * 8 + tq;
                ahi[i][0] = ah[b0i];     ahi[i][1] = ah[b1i];
                ahi[i][2] = ah[b0i + 4]; ahi[i][3] = ah[b1i + 4];
                alo[i][0] = al[b0i];     alo[i][1] = al[b1i];
                alo[i][2] = al[b0i + 4]; alo[i][3] = al[b1i + 4];
            }
            uint32_t bhi[4][2], blo[4][2];
            int k16 = t * 2 + kk;
            #pragma unroll
            for (int j = 0; j < 4; j++) {
                int nn = wn * 32 + j * 8 + g;
                int bi = nn * BH_S + k16 * 8 + tq;
                bhi[j][0] = smu[OFF_BHI + bi]; bhi[j][1] = smu[OFF_BHI + bi + 4];
                blo[j][0] = smu[OFF_BLO + bi]; blo[j][1] = smu[OFF_BLO + bi + 4];
            }
            #pragma unroll
            for (int i = 0; i < 4; i++)
                #pragma unroll
                for (int j = 0; j < 4; j++) {
                    MMA_F16(acc[i][j], ahi[i][0], ahi[i][1], ahi[i][2], ahi[i][3], bhi[j][0], bhi[j][1]);
                    MMA_F16(acc[i][j], ahi[i][0], ahi[i][1], ahi[i][2], ahi[i][3], blo[j][0], blo[j][1]);
                    MMA_F16(acc[i][j], alo[i][0], alo[i][1], alo[i][2], alo[i][3], bhi[j][0], bhi[j][1]);
                }
        }

        if (t < 3) {
            __syncthreads();
            if (t + 2 < 4) load_a(t + 2, t & 1);
            asm volatile("cp.async.wait_group %0;" :: "n"(1));
            if (t == 2) asm volatile("cp.async.wait_group 0;");
            __syncthreads();
        }
    }

    // ---- fused epilogue: a-part -> fp32 + b1 bias; (b,c) pair -> d = (c + b3) - s*b ----
    #pragma unroll
    for (int i = 0; i < 4; i++) {
        int gm0 = row0 + wm * 64 + i * 16 + g;
        int gm1 = gm0 + 8;
        float s0 = (gm0 < M) ? svec[gm0] : 0.f;
        float s1 = (gm1 < M) ? svec[gm1] : 0.f;
        #pragma unroll
        for (int j = 0; j < 4; j++) {
            int gn = col0 + wn * 32 + j * 8 + 2 * tq;
            if (gn >= Ncol) continue;
            if (gn < AC) {
                float2 bb = *reinterpret_cast<const float2*>(bias + gn);
                if (gm0 < M) {
                    float2 v0 = make_float2(acc[i][j][0] + bb.x, acc[i][j][1] + bb.y);
                    *reinterpret_cast<float2*>(out + (size_t)gm0 * OS + gn) = v0;
                }
                if (gm1 < M) {
                    float2 v1 = make_float2(acc[i][j][2] + bb.x, acc[i][j][3] + bb.y);
                    *reinterpret_cast<float2*>(out + (size_t)gm1 * OS + gn) = v1;
                }
            } else {
                int u = (gn - AC) >> 1;
                float b3v = bias[gn + 1];
                if (gm0 < M)
                    out[(size_t)gm0 * OS + AC + u] = (acc[i][j][1] + b3v) - s0 * acc[i][j][0];
                if (gm1 < M)
                    out[(size_t)gm1 * OS + AC + u] = (acc[i][j][3] + b3v) - s1 * acc[i][j][2];
            }
        }
    }
}

// ---------------- SpMM F=128: fp32 gather, writes next layer's split fp16 activations ----------------
__global__ __launch_bounds__(256) void spmm128_kernel(const float* __restrict__ ad,
                                                      __half* __restrict__ hhi,
                                                      __half* __restrict__ hlo) {
    const int F = 128;
    const int stride = 2 * F;
    int w = blockIdx.x * 8 + (threadIdx.x >> 5);
    if (w >= NN) return;
    int lane = threadIdx.x & 31;
    int fbase = lane * 4;

    float4 acc = make_float4(0.f, 0.f, 0.f, 0.f);
    int beg = g_rowptr[w], end = g_rowptr[w + 1];
    int e = beg;
    for (; e + 3 < end; e += 4) {
        int   s0 = g_src[e],   s1 = g_src[e+1], s2 = g_src[e+2], s3 = g_src[e+3];
        float w0 = g_ew[e],    w1 = g_ew[e+1],  w2 = g_ew[e+2],  w3 = g_ew[e+3];
        float4 a0 = *reinterpret_cast<const float4*>(ad + (size_t)s0 * stride + fbase);
        float4 a1 = *reinterpret_cast<const float4*>(ad + (size_t)s1 * stride + fbase);
        float4 a2 = *reinterpret_cast<const float4*>(ad + (size_t)s2 * stride + fbase);
        float4 a3 = *reinterpret_cast<const float4*>(ad + (size_t)s3 * stride + fbase);
        acc.x += w0 * a0.x + w1 * a1.x + w2 * a2.x + w3 * a3.x;
        acc.y += w0 * a0.y + w1 * a1.y + w2 * a2.y + w3 * a3.y;
        acc.z += w0 * a0.z + w1 * a1.z + w2 * a2.z + w3 * a3.z;
        acc.w += w0 * a0.w + w1 * a1.w + w2 * a2.w + w3 * a3.w;
    }
    for (; e < end; e++) {
        int   s0 = g_src[e];
        float w0 = g_ew[e];
        float4 a0 = *reinterpret_cast<const float4*>(ad + (size_t)s0 * stride + fbase);
        acc.x += w0 * a0.x; acc.y += w0 * a0.y; acc.z += w0 * a0.z; acc.w += w0 * a0.w;
    }
    float4 dv = *reinterpret_cast<const float4*>(ad + (size_t)w * stride + F + fbase);
    float v[4];
    v[0] = acc.x + dv.x;
    v[1] = acc.y + dv.y;
    v[2] = acc.z + dv.z;
    v[3] = acc.w + dv.w;
    #pragma unroll
    for (int i = 0; i < 4; i++)
        v[i] = v[i] > 0.f ? v[i] : 0.1f * v[i];

    __half2 h01 = __float22half2_rn(make_float2(v[0], v[1]));
    __half2 h23 = __float22half2_rn(make_float2(v[2], v[3]));
    float2 f01 = __half22float2(h01);
    float2 f23 = __half22float2(h23);
    __half2 l01 = __float22half2_rn(make_float2(v[0] - f01.x, v[1] - f01.y));
    __half2 l23 = __float22half2_rn(make_float2(v[2] - f23.x, v[3] - f23.y));
    uint2 uh = make_uint2(*reinterpret_cast<uint32_t*>(&h01), *reinterpret_cast<uint32_t*>(&h23));
    uint2 ul = make_uint2(*reinterpret_cast<uint32_t*>(&l01), *reinterpret_cast<uint32_t*>(&l23));
    *reinterpret_cast<uint2*>(hhi + (size_t)w * F + fbase) = uh;
    *reinterpret_cast<uint2*>(hlo + (size_t)w * F + fbase) = ul;
}

// ---------------- SpMM F=64 (final layer): fp32 gather, fp32 out, lrelu+sigmoid ----------------
__global__ __launch_bounds__(256) void spmm64_kernel(const float* __restrict__ ad,
                                                     float* __restrict__ out) {
    const int F = 64;
    const int stride = 2 * F;
    int w = blockIdx.x * 8 + (threadIdx.x >> 5);
    if (w >= NN) return;
    int lane = threadIdx.x & 31;
    int fbase = lane * 2;

    float2 acc = make_float2(0.f, 0.f);
    int beg = g_rowptr[w], end = g_rowptr[w + 1];
    int e = beg;
    for (; e + 3 < end; e += 4) {
        int   s0 = g_src[e],   s1 = g_src[e+1], s2 = g_src[e+2], s3 = g_src[e+3];
        float w0 = g_ew[e],    w1 = g_ew[e+1],  w2 = g_ew[e+2],  w3 = g_ew[e+3];
        float2 a0 = *reinterpret_cast<const float2*>(ad + (size_t)s0 * stride + fbase);
        float2 a1 = *reinterpret_cast<const float2*>(ad + (size_t)s1 * stride + fbase);
        float2 a2 = *reinterpret_cast<const float2*>(ad + (size_t)s2 * stride + fbase);
        float2 a3 = *reinterpret_cast<const float2*>(ad + (size_t)s3 * stride + fbase);
        acc.x += w0 * a0.x + w1 * a1.x + w2 * a2.x + w3 * a3.x;
        acc.y += w0 * a0.y + w1 * a1.y + w2 * a2.y + w3 * a3.y;
    }
    for (; e < end; e++) {
        int   s0 = g_src[e];
        float w0 = g_ew[e];
        float2 a0 = *reinterpret_cast<const float2*>(ad + (size_t)s0 * stride + fbase);
        acc.x += w0 * a0.x; acc.y += w0 * a0.y;
    }
    float2 dv = *reinterpret_cast<const float2*>(ad + (size_t)w * stride + F + fbase);
    float v[2];
    v[0] = acc.x + dv.x;
    v[1] = acc.y + dv.y;
    #pragma unroll
    for (int i = 0; i < 2; i++) {
        float t = v[i] > 0.f ? v[i] : 0.1f * v[i];
        v[i] = 1.f / (1.f + expf(-t));
    }
    *reinterpret_cast<float2*>(out + (size_t)w * F + fbase) = make_float2(v[0], v[1]);
}

// ---------------- host launch ----------------
extern "C" void kernel_launch(void* const* d_in, const int* in_sizes, int n_in,
                              void* d_out, int out_size) {
    const float* x  = (const float*)d_in[0];
    const void*  ei = d_in[1];
    const float* ea = (const float*)d_in[2];
    const float* W1_in  = (const float*)d_in[4];
    const float* b1_in  = (const float*)d_in[5];
    const float* W2_in  = (const float*)d_in[6];
    const float* W3_in  = (const float*)d_in[7];
    const float* b3_in  = (const float*)d_in[8];
    const float* W1_mid = (const float*)d_in[9];
    const float* b1_mid = (const float*)d_in[10];
    const float* W2_mid = (const float*)d_in[11];
    const float* W3_mid = (const float*)d_in[12];
    const float* b3_mid = (const float*)d_in[13];
    const float* W1_out = (const float*)d_in[14];
    const float* b1_out = (const float*)d_in[15];
    const float* W2_out = (const float*)d_in[16];
    const float* W3_out = (const float*)d_in[17];
    const float* b3_out = (const float*)d_in[18];

    float* out = (float*)d_out;

    float *d_abc, *d_b0, *d_b1, *d_b2, *d_s;
    __half *d_Ahi, *d_Alo, *d_Wh0, *d_Wl0, *d_Wh1, *d_Wl1, *d_Wh2, *d_Wl2;
    cudaGetSymbolAddress((void**)&d_abc, g_abc);
    cudaGetSymbolAddress((void**)&d_Ahi, g_Ahi);
    cudaGetSymbolAddress((void**)&d_Alo, g_Alo);
    cudaGetSymbolAddress((void**)&d_Wh0, g_Wthi0);
    cudaGetSymbolAddress((void**)&d_Wl0, g_Wtlo0);
    cudaGetSymbolAddress((void**)&d_Wh1, g_Wthi1);
    cudaGetSymbolAddress((void**)&d_Wl1, g_Wtlo1);
    cudaGetSymbolAddress((void**)&d_Wh2, g_Wthi2);
    cudaGetSymbolAddress((void**)&d_Wl2, g_Wtlo2);
    cudaGetSymbolAddress((void**)&d_b0,  g_bcat0);
    cudaGetSymbolAddress((void**)&d_b1,  g_bcat1);
    cudaGetSymbolAddress((void**)&d_b2,  g_bcat2);
    cudaGetSymbolAddress((void**)&d_s,   g_s);

    cudaFuncSetAttribute(tgemm_kernel, cudaFuncAttributeMaxDynamicSharedMemorySize, TG_SMEM);

    // --- one-time stream/event setup (outside capture; no device-memory allocation) ---
    static cudaStream_t s2 = nullptr;
    static cudaEvent_t evStart = nullptr, evPack = nullptr, evHist = nullptr, evCSR = nullptr;
    if (s2 == nullptr) {
        cudaStreamCreateWithFlags(&s2, cudaStreamNonBlocking);
        cudaEventCreateWithFlags(&evStart, cudaEventDisableTiming);
        cudaEventCreateWithFlags(&evPack,  cudaEventDisableTiming);
        cudaEventCreateWithFlags(&evHist,  cudaEventDisableTiming);
        cudaEventCreateWithFlags(&evCSR,   cudaEventDisableTiming);
    }

    // --- fork: side stream does weight packing + x split while main does zero+hist ---
    cudaEventRecord(evStart, 0);
    cudaStreamWaitEvent(s2, evStart, 0);
    pack_w_kernel<<<(F_IN * WID + 255) / 256, 256, 0, s2>>>(W1_in,  b1_in,  W2_in,  W3_in,  b3_in,  F_IN, WID,   d_Wh0, d_Wl0, d_b0);
    pack_w_kernel<<<(WID * WID + 255) / 256, 256, 0, s2>>>(W1_mid, b1_mid, W2_mid, W3_mid, b3_mid, WID,  WID,   d_Wh1, d_Wl1, d_b1);
    pack_w_kernel<<<(WID * F_OUT + 255) / 256, 256, 0, s2>>>(W1_out, b1_out, W2_out, W3_out, b3_out, WID, F_OUT, d_Wh2, d_Wl2, d_b2);
    convert_x_kernel<<<(NN * KK / 4 + 255) / 256, 256, 0, s2>>>((const float4*)x, NN * KK / 4);
    cudaEventRecord(evPack, s2);

    zero_kernel<<<(NN + 255) / 256, 256>>>((const int*)ei);
    hist_kernel<<<(EE + 255) / 256, 256>>>(ei, ea);
    cudaEventRecord(evHist, 0);

    // side stream: CSR chain (needs hist) — overlaps with layer-0 GEMM on main
    cudaStreamWaitEvent(s2, evHist, 0);
    scan1_kernel<<<SCAN_NB, SCAN_B, 0, s2>>>();
    scan3_kernel<<<SCAN_NB, SCAN_B, 0, s2>>>();
    scatter_kernel<<<(EE + 255) / 256, 256, 0, s2>>>(ei, ea);
    cudaEventRecord(evCSR, s2);

    const int spmm_blocks = (NN + 7) / 8;
    const int grid_m = (NN + 127) / 128;

    // --- layer 0 (in): GEMM needs pack/convert (evPack) + hist (already ordered on main) ---
    cudaStreamWaitEvent(0, evPack, 0);
    {
        dim3 grid(grid_m, (3 * WID + 127) / 128);
        tgemm_kernel<<<grid, 256, TG_SMEM>>>(d_Ahi, d_Alo, d_Wh0, d_Wl0, d_b0, d_s, NN, WID, d_abc);
    }
    cudaStreamWaitEvent(0, evCSR, 0);   // join CSR branch before first SpMM
    spmm128_kernel<<<spmm_blocks, 256>>>(d_abc, d_Ahi, d_Alo);

    // --- layers 1,2 (mid): serial on main ---
    for (int l = 0; l < 2; l++) {
        dim3 grid(grid_m, (3 * WID + 127) / 128);
        tgemm_kernel<<<grid, 256, TG_SMEM>>>(d_Ahi, d_Alo, d_Wh1, d_Wl1, d_b1, d_s, NN, WID, d_abc);
        spmm128_kernel<<<spmm_blocks, 256>>>(d_abc, d_Ahi, d_Alo);
    }

    // --- layer 3 (out): lrelu+sigmoid, fp32 out ---
    {
        dim3 grid(grid_m, (3 * F_OUT + 127) / 128);
        tgemm_kernel<<<grid, 256, TG_SMEM>>>(d_Ahi, d_Alo, d_Wh2, d_Wl2, d_b2, d_s, NN, F_OUT, d_abc);
        spmm64_kernel<<<spmm_blocks, 256>>>(d_abc, out);
    }
}

// round 15
// speedup vs baseline: 1.0564x; 1.0047x over previous
#include <cuda_runtime.h>
#include <cuda_bf16.h>
#include <cuda_fp16.h>
#include <math.h>
#include <stdint.h>

// Problem constants (fixed by setup_inputs)
#define NN      50000
#define EE      800000
#define F_IN    128
#define WID     128
#define F_OUT   64
#define KK      128          // inner dim is 128 for every layer

#define SCAN_B  1024
#define SCAN_NB ((NN + SCAN_B - 1) / SCAN_B)   // 49

// k-layout permutation: within each 8-u32 (k16) group, u32 at position p moves to
// P(p) = 2*(p&3) + (p>>2).  This makes the two words of every m16n8k16 fragment
// (k-pairs 2tq and 2tq+8) ADJACENT in memory -> single LDS.64 per fragment.
__device__ __forceinline__ int perm_u32(int p) {            // p = u32 pos within row
    int q = p & 7;
    return (p & ~7) + 2 * (q & 3) + (q >> 2);
}
// half-index version (for scalar writes in pack_w)
__device__ __forceinline__ int perm_half(int k) {           // k = half pos within row
    int u = (k >> 1) & 7;
    int np = 2 * (u & 3) + (u >> 2);
    return (k & ~15) + np * 2 + (k & 1);
}

// ---------------- device scratch (no allocation allowed) ----------------
__device__ __align__(16) __half g_Ahi[NN * KK];     // split activations, permuted k-layout
__device__ __align__(16) __half g_Alo[NN * KK];
__device__ float g_abc[NN * (3 * WID)];             // GEMM output: a | d (2*WID used)
__device__ __align__(16) __half g_Wthi0[3 * WID * KK];  // pre-split transposed weights [Ncol][K], permuted
__device__ __align__(16) __half g_Wtlo0[3 * WID * KK];
__device__ __align__(16) __half g_Wthi1[3 * WID * KK];
__device__ __align__(16) __half g_Wtlo1[3 * WID * KK];
__device__ __align__(16) __half g_Wthi2[3 * F_OUT * KK];
__device__ __align__(16) __half g_Wtlo2[3 * F_OUT * KK];
__device__ float g_bcat0[3 * WID];
__device__ float g_bcat1[3 * WID];
__device__ float g_bcat2[3 * F_OUT];
__device__ float g_s[NN];
__device__ int   g_deg[NN];
__device__ int   g_rowptr[NN + 1];
__device__ int   g_cursor[NN];
__device__ int   g_bsum[SCAN_NB];
__device__ int   g_src[EE];
__device__ float g_ew[EE];
__device__ int   g_is64;

__device__ __forceinline__ int edge_idx(const void* ei, int idx) {
    if (g_is64) return (int)((const long long*)ei)[idx];
    return ((const int*)ei)[idx];
}

__device__ __forceinline__ void split1(float v, __half& hi, __half& lo) {
    hi = __float2half_rn(v);
    lo = __float2half_rn(v - __half2float(hi));
}

// store one u32 (2 halves) into a permuted row at logical u32 position p
__device__ __forceinline__ void store_perm_u32(__half* base, size_t row, int p, uint32_t val) {
    int np = perm_u32(p);
    *reinterpret_cast<uint32_t*>(base + row * KK + np * 2) = val;
}

// ---------------- preprocessing ----------------
__global__ void zero_kernel(const int* __restrict__ ei_raw) {
    int i = blockIdx.x * blockDim.x + threadIdx.x;
    if (i < NN) { g_deg[i] = 0; g_s[i] = 0.f; }
    if (blockIdx.x == 0 && threadIdx.x == 0) {
        int is64 = 1;
        for (int t = 0; t < 64; t++)
            if (ei_raw[2 * t + 1] != 0) { is64 = 0; break; }
        g_is64 = is64;
    }
}

// split x into fp16 hi/lo (one shot, layer-0 input) — permuted k-layout
__global__ void convert_x_kernel(const float4* __restrict__ x4, int n4) {
    int i = blockIdx.x * blockDim.x + threadIdx.x;
    if (i >= n4) return;
    float4 v = x4[i];
    __half2 h01 = __float22half2_rn(make_float2(v.x, v.y));
    __half2 h23 = __float22half2_rn(make_float2(v.z, v.w));
    float2 f01 = __half22float2(h01);
    float2 f23 = __half22float2(h23);
    __half2 l01 = __float22half2_rn(make_float2(v.x - f01.x, v.y - f01.y));
    __half2 l23 = __float22half2_rn(make_float2(v.z - f23.x, v.w - f23.y));
    size_t row = (size_t)(4 * i) / KK;          // 4 floats per thread, KK halves per row
    int p0 = ((4 * i) % KK) >> 1;               // logical u32 position (even)
    store_perm_u32(g_Ahi, row, p0,     *reinterpret_cast<uint32_t*>(&h01));
    store_perm_u32(g_Ahi, row, p0 + 1, *reinterpret_cast<uint32_t*>(&h23));
    store_perm_u32(g_Alo, row, p0,     *reinterpret_cast<uint32_t*>(&l01));
    store_perm_u32(g_Alo, row, p0 + 1, *reinterpret_cast<uint32_t*>(&l23));
}

__global__ void hist_kernel(const void* __restrict__ ei,
                            const float* __restrict__ ea) {
    int e = blockIdx.x * blockDim.x + threadIdx.x;
    if (e < EE) {
        int dst = edge_idx(ei, EE + e);
        if ((unsigned)dst >= NN) return;
        atomicAdd(&g_deg[dst], 1);
        atomicAdd(&g_s[dst], ea[e]);
    }
}

__global__ __launch_bounds__(SCAN_B) void scan1_kernel() {
    __shared__ int wsum[32];
    int i = blockIdx.x * SCAN_B + threadIdx.x;
    int lane = threadIdx.x & 31;
    int wid  = threadIdx.x >> 5;
    int v = (i < NN) ? g_deg[i] : 0;
    int incl = v;
    #pragma unroll
    for (int off = 1; off < 32; off <<= 1) {
        int t = __shfl_up_sync(0xffffffffu, incl, off);
        if (lane >= off) incl += t;
    }
    if (lane == 31) wsum[wid] = incl;
    __syncthreads();
    if (wid == 0) {
        int s = wsum[lane];
        #pragma unroll
        for (int off = 1; off < 32; off <<= 1) {
            int t = __shfl_up_sync(0xffffffffu, s, off);
            if (lane >= off) s += t;
        }
        wsum[lane] = s;
    }
    __syncthreads();
    if (wid > 0) incl += wsum[wid - 1];
    if (i < NN) g_rowptr[i + 1] = incl;
    if (threadIdx.x == SCAN_B - 1) g_bsum[blockIdx.x] = incl;
}

// scan3: apply per-block carry computed locally from g_bsum (no separate scan2 launch)
__global__ __launch_bounds__(SCAN_B) void scan3_kernel() {
    __shared__ int boff_s;
    if (threadIdx.x == 0) {
        int run = 0;
        for (int b = 0; b < blockIdx.x; b++) run += g_bsum[b];
        boff_s = run;
    }
    __syncthreads();
    int i = blockIdx.x * SCAN_B + threadIdx.x;
    if (i < NN) {
        int rp = g_rowptr[i + 1] + boff_s;
        g_rowptr[i + 1] = rp;
        g_cursor[i] = rp - g_deg[i];
    }
    if (i == 0) g_rowptr[0] = 0;
}

__global__ void scatter_kernel(const void* __restrict__ ei,
                               const float* __restrict__ ea) {
    int e = blockIdx.x * blockDim.x + threadIdx.x;
    if (e < EE) {
        int src = edge_idx(ei, e);
        int dst = edge_idx(ei, EE + e);
        if ((unsigned)src >= NN || (unsigned)dst >= NN) return;
        int pos = atomicAdd(&g_cursor[dst], 1);
        g_src[pos] = src;
        g_ew[pos]  = ea[e];
    }
}

// ------- weight packing: transposed + pre-split + permuted k-layout -------
__global__ void pack_w_kernel(const float* __restrict__ W1, const float* __restrict__ b1,
                              const float* __restrict__ W2,
                              const float* __restrict__ W3, const float* __restrict__ b3,
                              int K, int C,
                              __half* __restrict__ Wthi, __half* __restrict__ Wtlo,
                              float* __restrict__ bcat) {
    int i = blockIdx.x * blockDim.x + threadIdx.x;
    int total = K * C;
    if (i < total) {
        int k = i / C, c = i % C;
        int kp = perm_half(k);
        __half h, l;
        split1(W1[i], h, l);
        Wthi[(size_t)c * KK + kp] = h;               Wtlo[(size_t)c * KK + kp] = l;
        split1(W2[i], h, l);
        Wthi[(size_t)(C + 2 * c) * KK + kp] = h;     Wtlo[(size_t)(C + 2 * c) * KK + kp] = l;
        split1(W3[i], h, l);
        Wthi[(size_t)(C + 2 * c + 1) * KK + kp] = h; Wtlo[(size_t)(C + 2 * c + 1) * KK + kp] = l;
    }
    if (i < C) {
        bcat[i]             = b1[i];
        bcat[C + 2 * i]     = 0.f;
        bcat[C + 2 * i + 1] = b3[i];
    }
}

// ========== tensor-core GEMM (3xFP16, pre-split + permuted operands, LDS.64 frags) ==========
#define AH_S 20                     // u32 per A-row per stage (16 data + 4 pad)
#define BH_S 68                     // u32 per B-row full-K (64 data + 4 pad)
#define OFF_ALO (2 * 128 * AH_S)    // 5120 u32
#define OFF_BHI (2 * OFF_ALO)       // 10240
#define OFF_BLO (OFF_BHI + 128 * BH_S)   // 18944
#define TG_SMEM ((OFF_BLO + 128 * BH_S) * 4)  // 110592 bytes

#define MMA_F16(d, a0, a1, a2, a3, b0, b1)                                              \
    asm volatile("mma.sync.aligned.m16n8k16.row.col.f32.f16.f16.f32 "                    \
                 "{%0,%1,%2,%3},{%4,%5,%6,%7},{%8,%9},{%0,%1,%2,%3};"                    \
                 : "+f"(d[0]), "+f"(d[1]), "+f"(d[2]), "+f"(d[3])                        \
                 : "r"(a0), "r"(a1), "r"(a2), "r"(a3), "r"(b0), "r"(b1))

__global__ __launch_bounds__(256, 1) void tgemm_kernel(const __half* __restrict__ Ahi,
                                                       const __half* __restrict__ Alo,
                                                       const __half* __restrict__ Wthi,
                                                       const __half* __restrict__ Wtlo,
                                                       const float* __restrict__ bias,
                                                       const float* __restrict__ svec,
                                                       int M, int AC,
                                                       float* __restrict__ out) {
    extern __shared__ uint32_t smu[];

    const int Ncol = 3 * AC;
    const int OS   = 2 * AC;
    const int tid = threadIdx.x;
    const int lane = tid & 31;
    const int g  = lane >> 2;
    const int tq = lane & 3;
    const int warp = tid >> 5;
    const int wm = warp & 1;
    const int wn = warp >> 1;
    const int row0 = blockIdx.x * 128;
    const int col0 = blockIdx.y * 128;

    const uint32_t sb = (uint32_t)__cvta_generic_to_shared(smu);

    auto load_a = [&](int s, int buf) {
        #pragma unroll
        for (int p = 0; p < 2; p++) {
            int f = tid + p * 256;
            int row = f >> 2, c = f & 3;
            bool valid = (row0 + row) < M;
            size_t gof = (valid ? (size_t)(row0 + row) : 0) * KK + s * 32 + c * 8;
            int bytes = valid ? 16 : 0;
            uint32_t du = (uint32_t)(buf * 128 * AH_S + row * AH_S + c * 4);
            asm volatile("cp.async.ca.shared.global [%0], [%1], 16, %2;"
                         :: "r"(sb + du * 4), "l"(Ahi + gof), "r"(bytes));
            asm volatile("cp.async.ca.shared.global [%0], [%1], 16, %2;"
                         :: "r"(sb + (OFF_ALO + du) * 4), "l"(Alo + gof), "r"(bytes));
        }
        asm volatile("cp.async.commit_group;");
    };

    auto load_b = [&]() {
        #pragma unroll
        for (int p = 0; p < 8; p++) {
            int f = tid + p * 256;
            int n = f >> 4, c = f & 15;
            bool valid = (col0 + n) < Ncol;
            size_t gof = (valid ? (size_t)(col0 + n) : 0) * KK + c * 8;
            int bytes = valid ? 16 : 0;
            uint32_t du = (uint32_t)(n * BH_S + c * 4);
            asm volatile("cp.async.ca.shared.global [%0], [%1], 16, %2;"
                         :: "r"(sb + (OFF_BHI + du) * 4), "l"(Wthi + gof), "r"(bytes));
            asm volatile("cp.async.ca.shared.global [%0], [%1], 16, %2;"
                         :: "r"(sb + (OFF_BLO + du) * 4), "l"(Wtlo + gof), "r"(bytes));
        }
        asm volatile("cp.async.commit_group;");
    };

    load_a(0, 0);
    load_b();
    load_a(1, 1);
    asm volatile("cp.async.wait_group 1;");
    __syncthreads();

    float acc[4][4][4];
    #pragma unroll
    for (int i = 0; i < 4; i++)
        #pragma unroll
        for (int j = 0; j < 4; j++)
            #pragma unroll
            for (int q = 0; q < 4; q++) acc[i][j][q] = 0.f;

    #pragma unroll
    for (int t = 0; t < 4; t++) {
        const uint32_t* ah = smu + (t & 1) * (128 * AH_S);
        const uint32_t* al = ah + OFF_ALO;

        #pragma unroll
        for (int kk = 0; kk < 2; kk++) {
            // permuted layout: frag word-pair (k-pairs 2tq, 2tq+8) is adjacent -> LDS.64
            uint32_t ahi[4][4], alo[4][4];
            #pragma unroll
            for (int i = 0; i < 4; i++) {
                int r0 = wm * 64 + i * 16 + g;
                int i0 = r0 * AH_S + kk * 8 + 2 * tq;
                int i1 = (r0 + 8) * AH_S + kk * 8 + 2 * tq;
                uint2 h0 = *reinterpret_cast<const uint2*>(&ah[i0]);
                uint2 h1 = *reinterpret_cast<const uint2*>(&ah[i1]);
                uint2 l0 = *reinterpret_cast<const uint2*>(&al[i0]);
                uint2 l1 = *reinterpret_cast<const uint2*>(&al[i1]);
                ahi[i][0] = h0.x; ahi[i][2] = h0.y;
                ahi[i][1] = h1.x; ahi[i][3] = h1.y;
                alo[i][0] = l0.x; alo[i][2] = l0.y;
                alo[i][1] = l1.x; alo[i][3] = l1.y;
            }
            uint32_t bhi[4][2], blo[4][2];
            int k16 = t * 2 + kk;
            #pragma unroll
            for (int j = 0; j < 4; j++) {
                int nn = wn * 32 + j * 8 + g;
                int bi = nn * BH_S + k16 * 8 + 2 * tq;
                uint2 hb = *reinterpret_cast<const uint2*>(&smu[OFF_BHI + bi]);
                uint2 lb = *reinterpret_cast<const uint2*>(&smu[OFF_BLO + bi]);
                bhi[j][0] = hb.x; bhi[j][1] = hb.y;
                blo[j][0] = lb.x; blo[j][1] = lb.y;
            }
            #pragma unroll
            for (int i = 0; i < 4; i++)
                #pragma unroll
                for (int j = 0; j < 4; j++) {
                    MMA_F16(acc[i][j], ahi[i][0], ahi[i][1], ahi[i][2], ahi[i][3], bhi[j][0], bhi[j][1]);
                    MMA_F16(acc[i][j], ahi[i][0], ahi[i][1], ahi[i][2], ahi[i][3], blo[j][0], blo[j][1]);
                    MMA_F16(acc[i][j], alo[i][0], alo[i][1], alo[i][2], alo[i][3], bhi[j][0], bhi[j][1]);
                }
        }

        if (t < 3) {
            __syncthreads();
            if (t + 2 < 4) load_a(t + 2, t & 1);
            asm volatile("cp.async.wait_group %0;" :: "n"(1));
            if (t == 2) asm volatile("cp.async.wait_group 0;");
            __syncthreads();
        }
    }

    // ---- fused epilogue: a-part -> fp32 + b1 bias; (b,c) pair -> d = (c + b3) - s*b ----
    #pragma unroll
    for (int i = 0; i < 4; i++) {
        int gm0 = row0 + wm * 64 + i * 16 + g;
        int gm1 = gm0 + 8;
        float s0 = (gm0 < M) ? svec[gm0] : 0.f;
        float s1 = (gm1 < M) ? svec[gm1] : 0.f;
        #pragma unroll
        for (int j = 0; j < 4; j++) {
            int gn = col0 + wn * 32 + j * 8 + 2 * tq;
            if (gn >= Ncol) continue;
            if (gn < AC) {
                float2 bb = *reinterpret_cast<const float2*>(bias + gn);
                if (gm0 < M) {
                    float2 v0 = make_float2(acc[i][j][0] + bb.x, acc[i][j][1] + bb.y);
                    *reinterpret_cast<float2*>(out + (size_t)gm0 * OS + gn) = v0;
                }
                if (gm1 < M) {
                    float2 v1 = make_float2(acc[i][j][2] + bb.x, acc[i][j][3] + bb.y);
                    *reinterpret_cast<float2*>(out + (size_t)gm1 * OS + gn) = v1;
                }
            } else {
                int u = (gn - AC) >> 1;
                float b3v = bias[gn + 1];
                if (gm0 < M)
                    out[(size_t)gm0 * OS + AC + u] = (acc[i][j][1] + b3v) - s0 * acc[i][j][0];
                if (gm1 < M)
                    out[(size_t)gm1 * OS + AC + u] = (acc[i][j][3] + b3v) - s1 * acc[i][j][2];
            }
        }
    }
}

// ---------------- SpMM F=128: fp32 gather, writes next layer's permuted split fp16 activations ----------------
__global__ __launch_bounds__(256) void spmm128_kernel(const float* __restrict__ ad,
                                                      __half* __restrict__ hhi,
                                                      __half* __restrict__ hlo) {
    const int F = 128;
    const int stride = 2 * F;
    int w = blockIdx.x * 8 + (threadIdx.x >> 5);
    if (w >= NN) return;
    int lane = threadIdx.x & 31;
    int fbase = lane * 4;

    float4 acc = make_float4(0.f, 0.f, 0.f, 0.f);
    int beg = g_rowptr[w], end = g_rowptr[w + 1];
    int e = beg;
    for (; e + 3 < end; e += 4) {
        int   s0 = g_src[e],   s1 = g_src[e+1], s2 = g_src[e+2], s3 = g_src[e+3];
        float w0 = g_ew[e],    w1 = g_ew[e+1],  w2 = g_ew[e+2],  w3 = g_ew[e+3];
        float4 a0 = *reinterpret_cast<const float4*>(ad + (size_t)s0 * stride + fbase);
        float4 a1 = *reinterpret_cast<const float4*>(ad + (size_t)s1 * stride + fbase);
        float4 a2 = *reinterpret_cast<const float4*>(ad + (size_t)s2 * stride + fbase);
        float4 a3 = *reinterpret_cast<const float4*>(ad + (size_t)s3 * stride + fbase);
        acc.x += w0 * a0.x + w1 * a1.x + w2 * a2.x + w3 * a3.x;
        acc.y += w0 * a0.y + w1 * a1.y + w2 * a2.y + w3 * a3.y;
        acc.z += w0 * a0.z + w1 * a1.z + w2 * a2.z + w3 * a3.z;
        acc.w += w0 * a0.w + w1 * a1.w + w2 * a2.w + w3 * a3.w;
    }
    for (; e < end; e++) {
        int   s0 = g_src[e];
        float w0 = g_ew[e];
        float4 a0 = *reinterpret_cast<const float4*>(ad + (size_t)s0 * stride + fbase);
        acc.x += w0 * a0.x; acc.y += w0 * a0.y; acc.z += w0 * a0.z; acc.w += w0 * a0.w;
    }
    float4 dv = *reinterpret_cast<const float4*>(ad + (size_t)w * stride + F + fbase);
    float v[4];
    v[0] = acc.x + dv.x;
    v[1] = acc.y + dv.y;
    v[2] = acc.z + dv.z;
    v[3] = acc.w + dv.w;
    #pragma unroll
    for (int i = 0; i < 4; i++)
        v[i] = v[i] > 0.f ? v[i] : 0.1f * v[i];

    __half2 h01 = __float22half2_rn(make_float2(v[0], v[1]));
    __half2 h23 = __float22half2_rn(make_float2(v[2], v[3]));
    float2 f01 = __half22float2(h01);
    float2 f23 = __half22float2(h23);
    __half2 l01 = __float22half2_rn(make_float2(v[0] - f01.x, v[1] - f01.y));
    __half2 l23 = __float22half2_rn(make_float2(v[2] - f23.x, v[3] - f23.y));
    // permuted stores: this thread's 2 u32s sit at logical positions lane*2, lane*2+1
    int p0 = lane * 2;
    store_perm_u32(hhi, (size_t)w, p0,     *reinterpret_cast<uint32_t*>(&h01));
    store_perm_u32(hhi, (size_t)w, p0 + 1, *reinterpret_cast<uint32_t*>(&h23));
    store_perm_u32(hlo, (size_t)w, p0,     *reinterpret_cast<uint32_t*>(&l01));
    store_perm_u32(hlo, (size_t)w, p0 + 1, *reinterpret_cast<uint32_t*>(&l23));
}

// ---------------- SpMM F=64 (final layer): fp32 gather, fp32 out, lrelu+sigmoid ----------------
__global__ __launch_bounds__(256) void spmm64_kernel(const float* __restrict__ ad,
                                                     float* __restrict__ out) {
    const int F = 64;
    const int stride = 2 * F;
    int w = blockIdx.x * 8 + (threadIdx.x >> 5);
    if (w >= NN) return;
    int lane = threadIdx.x & 31;
    int fbase = lane * 2;

    float2 acc = make_float2(0.f, 0.f);
    int beg = g_rowptr[w], end = g_rowptr[w + 1];
    int e = beg;
    for (; e + 3 < end; e += 4) {
        int   s0 = g_src[e],   s1 = g_src[e+1], s2 = g_src[e+2], s3 = g_src[e+3];
        float w0 = g_ew[e],    w1 = g_ew[e+1],  w2 = g_ew[e+2],  w3 = g_ew[e+3];
        float2 a0 = *reinterpret_cast<const float2*>(ad + (size_t)s0 * stride + fbase);
        float2 a1 = *reinterpret_cast<const float2*>(ad + (size_t)s1 * stride + fbase);
        float2 a2 = *reinterpret_cast<const float2*>(ad + (size_t)s2 * stride + fbase);
        float2 a3 = *reinterpret_cast<const float2*>(ad + (size_t)s3 * stride + fbase);
        acc.x += w0 * a0.x + w1 * a1.x + w2 * a2.x + w3 * a3.x;
        acc.y += w0 * a0.y + w1 * a1.y + w2 * a2.y + w3 * a3.y;
    }
    for (; e < end; e++) {
        int   s0 = g_src[e];
        float w0 = g_ew[e];
        float2 a0 = *reinterpret_cast<const float2*>(ad + (size_t)s0 * stride + fbase);
        acc.x += w0 * a0.x; acc.y += w0 * a0.y;
    }
    float2 dv = *reinterpret_cast<const float2*>(ad + (size_t)w * stride + F + fbase);
    float v[2];
    v[0] = acc.x + dv.x;
    v[1] = acc.y + dv.y;
    #pragma unroll
    for (int i = 0; i < 2; i++) {
        float t = v[i] > 0.f ? v[i] : 0.1f * v[i];
        v[i] = 1.f / (1.f + expf(-t));
    }
    *reinterpret_cast<float2*>(out + (size_t)w * F + fbase) = make_float2(v[0], v[1]);
}

// ---------------- host launch ----------------
extern "C" void kernel_launch(void* const* d_in, const int* in_sizes, int n_in,
                              void* d_out, int out_size) {
    const float* x  = (const float*)d_in[0];
    const void*  ei = d_in[1];
    const float* ea = (const float*)d_in[2];
    const float* W1_in  = (const float*)d_in[4];
    const float* b1_in  = (const float*)d_in[5];
    const float* W2_in  = (const float*)d_in[6];
    const float* W3_in  = (const float*)d_in[7];
    const float* b3_in  = (const float*)d_in[8];
    const float* W1_mid = (const float*)d_in[9];
    const float* b1_mid = (const float*)d_in[10];
    const float* W2_mid = (const float*)d_in[11];
    const float* W3_mid = (const float*)d_in[12];
    const float* b3_mid = (const float*)d_in[13];
    const float* W1_out = (const float*)d_in[14];
    const float* b1_out = (const float*)d_in[15];
    const float* W2_out = (const float*)d_in[16];
    const float* W3_out = (const float*)d_in[17];
    const float* b3_out = (const float*)d_in[18];

    float* out = (float*)d_out;

    float *d_abc, *d_b0, *d_b1, *d_b2, *d_s;
    __half *d_Ahi, *d_Alo, *d_Wh0, *d_Wl0, *d_Wh1, *d_Wl1, *d_Wh2, *d_Wl2;
    cudaGetSymbolAddress((void**)&d_abc, g_abc);
    cudaGetSymbolAddress((void**)&d_Ahi, g_Ahi);
    cudaGetSymbolAddress((void**)&d_Alo, g_Alo);
    cudaGetSymbolAddress((void**)&d_Wh0, g_Wthi0);
    cudaGetSymbolAddress((void**)&d_Wl0, g_Wtlo0);
    cudaGetSymbolAddress((void**)&d_Wh1, g_Wthi1);
    cudaGetSymbolAddress((void**)&d_Wl1, g_Wtlo1);
    cudaGetSymbolAddress((void**)&d_Wh2, g_Wthi2);
    cudaGetSymbolAddress((void**)&d_Wl2, g_Wtlo2);
    cudaGetSymbolAddress((void**)&d_b0,  g_bcat0);
    cudaGetSymbolAddress((void**)&d_b1,  g_bcat1);
    cudaGetSymbolAddress((void**)&d_b2,  g_bcat2);
    cudaGetSymbolAddress((void**)&d_s,   g_s);

    cudaFuncSetAttribute(tgemm_kernel, cudaFuncAttributeMaxDynamicSharedMemorySize, TG_SMEM);

    // --- one-time stream/event setup (outside capture; no device-memory allocation) ---
    static cudaStream_t s2 = nullptr;
    static cudaEvent_t evStart = nullptr, evPack = nullptr, evHist = nullptr, evCSR = nullptr;
    if (s2 == nullptr) {
        cudaStreamCreateWithFlags(&s2, cudaStreamNonBlocking);
        cudaEventCreateWithFlags(&evStart, cudaEventDisableTiming);
        cudaEventCreateWithFlags(&evPack,  cudaEventDisableTiming);
        cudaEventCreateWithFlags(&evHist,  cudaEventDisableTiming);
        cudaEventCreateWithFlags(&evCSR,   cudaEventDisableTiming);
    }

    // --- fork: side stream does weight packing + x split while main does zero+hist ---
    cudaEventRecord(evStart, 0);
    cudaStreamWaitEvent(s2, evStart, 0);
    pack_w_kernel<<<(F_IN * WID + 255) / 256, 256, 0, s2>>>(W1_in,  b1_in,  W2_in,  W3_in,  b3_in,  F_IN, WID,   d_Wh0, d_Wl0, d_b0);
    pack_w_kernel<<<(WID * WID + 255) / 256, 256, 0, s2>>>(W1_mid, b1_mid, W2_mid, W3_mid, b3_mid, WID,  WID,   d_Wh1, d_Wl1, d_b1);
    pack_w_kernel<<<(WID * F_OUT + 255) / 256, 256, 0, s2>>>(W1_out, b1_out, W2_out, W3_out, b3_out, WID, F_OUT, d_Wh2, d_Wl2, d_b2);
    convert_x_kernel<<<(NN * KK / 4 + 255) / 256, 256, 0, s2>>>((const float4*)x, NN * KK / 4);
    cudaEventRecord(evPack, s2);

    zero_kernel<<<(NN + 255) / 256, 256>>>((const int*)ei);
    hist_kernel<<<(EE + 255) / 256, 256>>>(ei, ea);
    cudaEventRecord(evHist, 0);

    // side stream: CSR chain (needs hist) — overlaps with layer-0 GEMM on main
    cudaStreamWaitEvent(s2, evHist, 0);
    scan1_kernel<<<SCAN_NB, SCAN_B, 0, s2>>>();
    scan3_kernel<<<SCAN_NB, SCAN_B, 0, s2>>>();
    scatter_kernel<<<(EE + 255) / 256, 256, 0, s2>>>(ei, ea);
    cudaEventRecord(evCSR, s2);

    const int spmm_blocks = (NN + 7) / 8;
    const int grid_m = (NN + 127) / 128;

    // --- layer 0 (in): GEMM needs pack/convert (evPack) + hist (already ordered on main) ---
    cudaStreamWaitEvent(0, evPack, 0);
    {
        dim3 grid(grid_m, (3 * WID + 127) / 128);
        tgemm_kernel<<<grid, 256, TG_SMEM>>>(d_Ahi, d_Alo, d_Wh0, d_Wl0, d_b0, d_s, NN, WID, d_abc);
    }
    cudaStreamWaitEvent(0, evCSR, 0);   // join CSR branch before first SpMM
    spmm128_kernel<<<spmm_blocks, 256>>>(d_abc, d_Ahi, d_Alo);

    // --- layers 1,2 (mid): serial on main ---
    for (int l = 0; l < 2; l++) {
        dim3 grid(grid_m, (3 * WID + 127) / 128);
        tgemm_kernel<<<grid, 256, TG_SMEM>>>(d_Ahi, d_Alo, d_Wh1, d_Wl1, d_b1, d_s, NN, WID, d_abc);
        spmm128_kernel<<<spmm_blocks, 256>>>(d_abc, d_Ahi, d_Alo);
    }

    // --- layer 3 (out): lrelu+sigmoid, fp32 out ---
    {
        dim3 grid(grid_m, (3 * F_OUT + 127) / 128);
        tgemm_kernel<<<grid, 256, TG_SMEM>>>(d_Ahi, d_Alo, d_Wh2, d_Wl2, d_b2, d_s, NN, F_OUT, d_abc);
        spmm64_kernel<<<spmm_blocks, 256>>>(d_abc, out);
    }
}

// round 17
// speedup vs baseline: 1.0651x; 1.0082x over previous
#include <cuda_runtime.h>
#include <cuda_bf16.h>
#include <cuda_fp16.h>
#include <math.h>
#include <stdint.h>

// Problem constants (fixed by setup_inputs)
#define NN      50000
#define EE      800000
#define F_IN    128
#define WID     128
#define F_OUT   64
#define KK      128          // inner dim is 128 for every layer

#define SCAN_B  1024
#define SCAN_NB ((NN + SCAN_B - 1) / SCAN_B)   // 49

// k-layout permutation: within each 8-u32 (k16) group, u32 at position p moves to
// P(p) = 2*(p&3) + (p>>2) -> fragment word-pairs adjacent -> LDS.64 loads.
__device__ __forceinline__ int perm_u32(int p) {
    int q = p & 7;
    return (p & ~7) + 2 * (q & 3) + (q >> 2);
}
__device__ __forceinline__ int perm_half(int k) {
    int u = (k >> 1) & 7;
    int np = 2 * (u & 3) + (u >> 2);
    return (k & ~15) + np * 2 + (k & 1);
}

// ---------------- device scratch (no allocation allowed) ----------------
__device__ __align__(16) __half g_Ahi[NN * KK];     // split activations, permuted k-layout
__device__ __align__(16) __half g_Alo[NN * KK];
__device__ float g_abc[NN * (3 * WID)];             // GEMM output: a | d (2*WID used)
__device__ __align__(16) __half g_Wthi0[3 * WID * KK];  // pre-split transposed weights, permuted
__device__ __align__(16) __half g_Wtlo0[3 * WID * KK];
__device__ __align__(16) __half g_Wthi1[3 * WID * KK];
__device__ __align__(16) __half g_Wtlo1[3 * WID * KK];
__device__ __align__(16) __half g_Wthi2[3 * F_OUT * KK];
__device__ __align__(16) __half g_Wtlo2[3 * F_OUT * KK];
__device__ float g_bcat0[3 * WID];
__device__ float g_bcat1[3 * WID];
__device__ float g_bcat2[3 * F_OUT];
__device__ float g_s[NN];
__device__ int   g_deg[NN];
__device__ int   g_rowptr[NN + 1];
__device__ int   g_cursor[NN];
__device__ int   g_bsum[SCAN_NB];
__device__ int   g_src[EE];
__device__ float g_ew[EE];
__device__ int   g_is64;

__device__ __forceinline__ int edge_idx(const void* ei, int idx) {
    if (g_is64) return (int)((const long long*)ei)[idx];
    return ((const int*)ei)[idx];
}

__device__ __forceinline__ void split1(float v, __half& hi, __half& lo) {
    hi = __float2half_rn(v);
    lo = __float2half_rn(v - __half2float(hi));
}

__device__ __forceinline__ void store_perm_u32(__half* base, size_t row, int p, uint32_t val) {
    int np = perm_u32(p);
    *reinterpret_cast<uint32_t*>(base + row * KK + np * 2) = val;
}

// ---------------- preprocessing ----------------
__global__ void zero_kernel(const int* __restrict__ ei_raw) {
    int i = blockIdx.x * blockDim.x + threadIdx.x;
    if (i < NN) { g_deg[i] = 0; g_s[i] = 0.f; }
    if (blockIdx.x == 0 && threadIdx.x == 0) {
        int is64 = 1;
        for (int t = 0; t < 64; t++)
            if (ei_raw[2 * t + 1] != 0) { is64 = 0; break; }
        g_is64 = is64;
    }
}

__global__ void convert_x_kernel(const float4* __restrict__ x4, int n4) {
    int i = blockIdx.x * blockDim.x + threadIdx.x;
    if (i >= n4) return;
    float4 v = x4[i];
    __half2 h01 = __float22half2_rn(make_float2(v.x, v.y));
    __half2 h23 = __float22half2_rn(make_float2(v.z, v.w));
    float2 f01 = __half22float2(h01);
    float2 f23 = __half22float2(h23);
    __half2 l01 = __float22half2_rn(make_float2(v.x - f01.x, v.y - f01.y));
    __half2 l23 = __float22half2_rn(make_float2(v.z - f23.x, v.w - f23.y));
    size_t row = (size_t)(4 * i) / KK;
    int p0 = ((4 * i) % KK) >> 1;
    store_perm_u32(g_Ahi, row, p0,     *reinterpret_cast<uint32_t*>(&h01));
    store_perm_u32(g_Ahi, row, p0 + 1, *reinterpret_cast<uint32_t*>(&h23));
    store_perm_u32(g_Alo, row, p0,     *reinterpret_cast<uint32_t*>(&l01));
    store_perm_u32(g_Alo, row, p0 + 1, *reinterpret_cast<uint32_t*>(&l23));
}

__global__ void hist_kernel(const void* __restrict__ ei,
                            const float* __restrict__ ea) {
    int e = blockIdx.x * blockDim.x + threadIdx.x;
    if (e < EE) {
        int dst = edge_idx(ei, EE + e);
        if ((unsigned)dst >= NN) return;
        atomicAdd(&g_deg[dst], 1);
        atomicAdd(&g_s[dst], ea[e]);
    }
}

__global__ __launch_bounds__(SCAN_B) void scan1_kernel() {
    __shared__ int wsum[32];
    int i = blockIdx.x * SCAN_B + threadIdx.x;
    int lane = threadIdx.x & 31;
    int wid  = threadIdx.x >> 5;
    int v = (i < NN) ? g_deg[i] : 0;
    int incl = v;
    #pragma unroll
    for (int off = 1; off < 32; off <<= 1) {
        int t = __shfl_up_sync(0xffffffffu, incl, off);
        if (lane >= off) incl += t;
    }
    if (lane == 31) wsum[wid] = incl;
    __syncthreads();
    if (wid == 0) {
        int s = wsum[lane];
        #pragma unroll
        for (int off = 1; off < 32; off <<= 1) {
            int t = __shfl_up_sync(0xffffffffu, s, off);
            if (lane >= off) s += t;
        }
        wsum[lane] = s;
    }
    __syncthreads();
    if (wid > 0) incl += wsum[wid - 1];
    if (i < NN) g_rowptr[i + 1] = incl;
    if (threadIdx.x == SCAN_B - 1) g_bsum[blockIdx.x] = incl;
}

__global__ __launch_bounds__(SCAN_B) void scan3_kernel() {
    __shared__ int boff_s;
    if (threadIdx.x == 0) {
        int run = 0;
        for (int b = 0; b < blockIdx.x; b++) run += g_bsum[b];
        boff_s = run;
    }
    __syncthreads();
    int i = blockIdx.x * SCAN_B + threadIdx.x;
    if (i < NN) {
        int rp = g_rowptr[i + 1] + boff_s;
        g_rowptr[i + 1] = rp;
        g_cursor[i] = rp - g_deg[i];
    }
    if (i == 0) g_rowptr[0] = 0;
}

__global__ void scatter_kernel(const void* __restrict__ ei,
                               const float* __restrict__ ea) {
    int e = blockIdx.x * blockDim.x + threadIdx.x;
    if (e < EE) {
        int src = edge_idx(ei, e);
        int dst = edge_idx(ei, EE + e);
        if ((unsigned)src >= NN || (unsigned)dst >= NN) return;
        int pos = atomicAdd(&g_cursor[dst], 1);
        g_src[pos] = src;
        g_ew[pos]  = ea[e];
    }
}

// ------- weight packing: transposed + pre-split + permuted k-layout -------
__global__ void pack_w_kernel(const float* __restrict__ W1, const float* __restrict__ b1,
                              const float* __restrict__ W2,
                              const float* __restrict__ W3, const float* __restrict__ b3,
                              int K, int C,
                              __half* __restrict__ Wthi, __half* __restrict__ Wtlo,
                              float* __restrict__ bcat) {
    int i = blockIdx.x * blockDim.x + threadIdx.x;
    int total = K * C;
    if (i < total) {
        int k = i / C, c = i % C;
        int kp = perm_half(k);
        __half h, l;
        split1(W1[i], h, l);
        Wthi[(size_t)c * KK + kp] = h;               Wtlo[(size_t)c * KK + kp] = l;
        split1(W2[i], h, l);
        Wthi[(size_t)(C + 2 * c) * KK + kp] = h;     Wtlo[(size_t)(C + 2 * c) * KK + kp] = l;
        split1(W3[i], h, l);
        Wthi[(size_t)(C + 2 * c + 1) * KK + kp] = h; Wtlo[(size_t)(C + 2 * c + 1) * KK + kp] = l;
    }
    if (i < C) {
        bcat[i]             = b1[i];
        bcat[C + 2 * i]     = 0.f;
        bcat[C + 2 * i + 1] = b3[i];
    }
}

// ========== tensor-core GEMM (3xFP16, permuted, A AND B double-buffered BK=32) ==========
// smem: 8 blocks of 128 rows x 20 u32 (16 data + 4 pad) = 80 KB -> 2 CTAs/SM.
#define ST_S   20                       // u32 per row per stage
#define BLK_U  (128 * ST_S)             // 2560 u32 per block
#define OFF_ALO2 (2 * BLK_U)            // 5120
#define OFF_BHI2 (4 * BLK_U)            // 10240
#define OFF_BLO2 (6 * BLK_U)            // 15360
#define TG_SMEM (8 * BLK_U * 4)         // 81920 bytes

#define MMA_F16(d, a0, a1, a2, a3, b0, b1)                                              \
    asm volatile("mma.sync.aligned.m16n8k16.row.col.f32.f16.f16.f32 "                    \
                 "{%0,%1,%2,%3},{%4,%5,%6,%7},{%8,%9},{%0,%1,%2,%3};"                    \
                 : "+f"(d[0]), "+f"(d[1]), "+f"(d[2]), "+f"(d[3])                        \
                 : "r"(a0), "r"(a1), "r"(a2), "r"(a3), "r"(b0), "r"(b1))

__global__ __launch_bounds__(256, 2) void tgemm_kernel(const __half* __restrict__ Ahi,
                                                       const __half* __restrict__ Alo,
                                                       const __half* __restrict__ Wthi,
                                                       const __half* __restrict__ Wtlo,
                                                       const float* __restrict__ bias,
                                                       const float* __restrict__ svec,
                                                       int M, int AC,
                                                       float* __restrict__ out) {
    extern __shared__ uint32_t smu[];

    const int Ncol = 3 * AC;
    const int OS   = 2 * AC;
    const int tid = threadIdx.x;
    const int lane = tid & 31;
    const int g  = lane >> 2;
    const int tq = lane & 3;
    const int warp = tid >> 5;
    const int wm = warp & 1;
    const int wn = warp >> 1;
    const int row0 = blockIdx.x * 128;
    const int col0 = blockIdx.y * 128;

    const uint32_t sb = (uint32_t)__cvta_generic_to_shared(smu);

    // one stage = A (hi+lo) + B (hi+lo), BK=32 halves (16 u32/row), one commit group
    auto load_stage = [&](int s, int buf) {
        #pragma unroll
        for (int p = 0; p < 2; p++) {
            int f = tid + p * 256;
            int row = f >> 2, c = f & 3;
            bool valid = (row0 + row) < M;
            size_t gof = (valid ? (size_t)(row0 + row) : 0) * KK + s * 32 + c * 8;
            int bytes = valid ? 16 : 0;
            uint32_t du = (uint32_t)(buf * BLK_U + row * ST_S + c * 4);
            asm volatile("cp.async.ca.shared.global [%0], [%1], 16, %2;"
                         :: "r"(sb + du * 4), "l"(Ahi + gof), "r"(bytes));
            asm volatile("cp.async.ca.shared.global [%0], [%1], 16, %2;"
                         :: "r"(sb + (OFF_ALO2 + du) * 4), "l"(Alo + gof), "r"(bytes));
        }
        #pragma unroll
        for (int p = 0; p < 2; p++) {
            int f = tid + p * 256;
            int n = f >> 2, c = f & 3;
            bool nval = (col0 + n) < Ncol;
            size_t gof = (nval ? (size_t)(col0 + n) : 0) * KK + s * 32 + c * 8;
            int bytes = nval ? 16 : 0;
            uint32_t du = (uint32_t)(buf * BLK_U + n * ST_S + c * 4);
            asm volatile("cp.async.ca.shared.global [%0], [%1], 16, %2;"
                         :: "r"(sb + (OFF_BHI2 + du) * 4), "l"(Wthi + gof), "r"(bytes));
            asm volatile("cp.async.ca.shared.global [%0], [%1], 16, %2;"
                         :: "r"(sb + (OFF_BLO2 + du) * 4), "l"(Wtlo + gof), "r"(bytes));
        }
        asm volatile("cp.async.commit_group;");
    };

    load_stage(0, 0);
    load_stage(1, 1);
    asm volatile("cp.async.wait_group 1;");
    __syncthreads();

    float acc[4][4][4];
    #pragma unroll
    for (int i = 0; i < 4; i++)
        #pragma unroll
        for (int j = 0; j < 4; j++)
            #pragma unroll
            for (int q = 0; q < 4; q++) acc[i][j][q] = 0.f;

    #pragma unroll
    for (int t = 0; t < 4; t++) {
        const uint32_t* ah = smu + (t & 1) * BLK_U;
        const uint32_t* al = ah + OFF_ALO2;
        const uint32_t* bh = smu + OFF_BHI2 + (t & 1) * BLK_U;
        const uint32_t* bl = bh + (OFF_BLO2 - OFF_BHI2);

        #pragma unroll
        for (int kk = 0; kk < 2; kk++) {
            uint32_t ahi[4][4], alo[4][4];
            #pragma unroll
            for (int i = 0; i < 4; i++) {
                int r0 = wm * 64 + i * 16 + g;
                int i0 = r0 * ST_S + kk * 8 + 2 * tq;
                int i1 = (r0 + 8) * ST_S + kk * 8 + 2 * tq;
                uint2 h0 = *reinterpret_cast<const uint2*>(&ah[i0]);
                uint2 h1 = *reinterpret_cast<const uint2*>(&ah[i1]);
                uint2 l0 = *reinterpret_cast<const uint2*>(&al[i0]);
                uint2 l1 = *reinterpret_cast<const uint2*>(&al[i1]);
                ahi[i][0] = h0.x; ahi[i][2] = h0.y;
                ahi[i][1] = h1.x; ahi[i][3] = h1.y;
                alo[i][0] = l0.x; alo[i][2] = l0.y;
                alo[i][1] = l1.x; alo[i][3] = l1.y;
            }
            uint32_t bhi[4][2], blo[4][2];
            #pragma unroll
            for (int j = 0; j < 4; j++) {
                int nn = wn * 32 + j * 8 + g;
                int bi = nn * ST_S + kk * 8 + 2 * tq;
                uint2 hb = *reinterpret_cast<const uint2*>(&bh[bi]);
                uint2 lb = *reinterpret_cast<const uint2*>(&bl[bi]);
                bhi[j][0] = hb.x; bhi[j][1] = hb.y;
                blo[j][0] = lb.x; blo[j][1] = lb.y;
            }
            #pragma unroll
            for (int i = 0; i < 4; i++)
                #pragma unroll
                for (int j = 0; j < 4; j++) {
                    MMA_F16(acc[i][j], ahi[i][0], ahi[i][1], ahi[i][2], ahi[i][3], bhi[j][0], bhi[j][1]);
                    MMA_F16(acc[i][j], ahi[i][0], ahi[i][1], ahi[i][2], ahi[i][3], blo[j][0], blo[j][1]);
                    MMA_F16(acc[i][j], alo[i][0], alo[i][1], alo[i][2], alo[i][3], bhi[j][0], bhi[j][1]);
                }
        }

        if (t < 3) {
            __syncthreads();
            if (t + 2 < 4) load_stage(t + 2, t & 1);
            asm volatile("cp.async.wait_group %0;" :: "n"(1));
            if (t == 2) asm volatile("cp.async.wait_group 0;");
            __syncthreads();
        }
    }

    // ---- fused epilogue: a-part -> fp32 + b1 bias; (b,c) pair -> d = (c + b3) - s*b ----
    #pragma unroll
    for (int i = 0; i < 4; i++) {
        int gm0 = row0 + wm * 64 + i * 16 + g;
        int gm1 = gm0 + 8;
        float s0 = (gm0 < M) ? svec[gm0] : 0.f;
        float s1 = (gm1 < M) ? svec[gm1] : 0.f;
        #pragma unroll
        for (int j = 0; j < 4; j++) {
            int gn = col0 + wn * 32 + j * 8 + 2 * tq;
            if (gn >= Ncol) continue;
            if (gn < AC) {
                float2 bb = *reinterpret_cast<const float2*>(bias + gn);
                if (gm0 < M) {
                    float2 v0 = make_float2(acc[i][j][0] + bb.x, acc[i][j][1] + bb.y);
                    *reinterpret_cast<float2*>(out + (size_t)gm0 * OS + gn) = v0;
                }
                if (gm1 < M) {
                    float2 v1 = make_float2(acc[i][j][2] + bb.x, acc[i][j][3] + bb.y);
                    *reinterpret_cast<float2*>(out + (size_t)gm1 * OS + gn) = v1;
                }
            } else {
                int u = (gn - AC) >> 1;
                float b3v = bias[gn + 1];
                if (gm0 < M)
                    out[(size_t)gm0 * OS + AC + u] = (acc[i][j][1] + b3v) - s0 * acc[i][j][0];
                if (gm1 < M)
                    out[(size_t)gm1 * OS + AC + u] = (acc[i][j][3] + b3v) - s1 * acc[i][j][2];
            }
        }
    }
}

// ---------------- SpMM F=128: fp32 gather, writes next layer's permuted split fp16 activations ----------------
__global__ __launch_bounds__(256) void spmm128_kernel(const float* __restrict__ ad,
                                                      __half* __restrict__ hhi,
                                                      __half* __restrict__ hlo) {
    const int F = 128;
    const int stride = 2 * F;
    int w = blockIdx.x * 8 + (threadIdx.x >> 5);
    if (w >= NN) return;
    int lane = threadIdx.x & 31;
    int fbase = lane * 4;

    float4 acc = make_float4(0.f, 0.f, 0.f, 0.f);
    int beg = g_rowptr[w], end = g_rowptr[w + 1];
    int e = beg;
    for (; e + 3 < end; e += 4) {
        int   s0 = g_src[e],   s1 = g_src[e+1], s2 = g_src[e+2], s3 = g_src[e+3];
        float w0 = g_ew[e],    w1 = g_ew[e+1],  w2 = g_ew[e+2],  w3 = g_ew[e+3];
        float4 a0 = *reinterpret_cast<const float4*>(ad + (size_t)s0 * stride + fbase);
        float4 a1 = *reinterpret_cast<const float4*>(ad + (size_t)s1 * stride + fbase);
        float4 a2 = *reinterpret_cast<const float4*>(ad + (size_t)s2 * stride + fbase);
        float4 a3 = *reinterpret_cast<const float4*>(ad + (size_t)s3 * stride + fbase);
        acc.x += w0 * a0.x + w1 * a1.x + w2 * a2.x + w3 * a3.x;
        acc.y += w0 * a0.y + w1 * a1.y + w2 * a2.y + w3 * a3.y;
        acc.z += w0 * a0.z + w1 * a1.z + w2 * a2.z + w3 * a3.z;
        acc.w += w0 * a0.w + w1 * a1.w + w2 * a2.w + w3 * a3.w;
    }
    for (; e < end; e++) {
        int   s0 = g_src[e];
        float w0 = g_ew[e];
        float4 a0 = *reinterpret_cast<const float4*>(ad + (size_t)s0 * stride + fbase);
        acc.x += w0 * a0.x; acc.y += w0 * a0.y; acc.z += w0 * a0.z; acc.w += w0 * a0.w;
    }
    float4 dv = *reinterpret_cast<const float4*>(ad + (size_t)w * stride + F + fbase);
    float v[4];
    v[0] = acc.x + dv.x;
    v[1] = acc.y + dv.y;
    v[2] = acc.z + dv.z;
    v[3] = acc.w + dv.w;
    #pragma unroll
    for (int i = 0; i < 4; i++)
        v[i] = v[i] > 0.f ? v[i] : 0.1f * v[i];

    __half2 h01 = __float22half2_rn(make_float2(v[0], v[1]));
    __half2 h23 = __float22half2_rn(make_float2(v[2], v[3]));
    float2 f01 = __half22float2(h01);
    float2 f23 = __half22float2(h23);
    __half2 l01 = __float22half2_rn(make_float2(v[0] - f01.x, v[1] - f01.y));
    __half2 l23 = __float22half2_rn(make_float2(v[2] - f23.x, v[3] - f23.y));
    int p0 = lane * 2;
    store_perm_u32(hhi, (size_t)w, p0,     *reinterpret_cast<uint32_t*>(&h01));
    store_perm_u32(hhi, (size_t)w, p0 + 1, *reinterpret_cast<uint32_t*>(&h23));
    store_perm_u32(hlo, (size_t)w, p0,     *reinterpret_cast<uint32_t*>(&l01));
    store_perm_u32(hlo, (size_t)w, p0 + 1, *reinterpret_cast<uint32_t*>(&l23));
}

// ---------------- SpMM F=64 (final layer): fp32 gather, fp32 out, lrelu+sigmoid ----------------
__global__ __launch_bounds__(256) void spmm64_kernel(const float* __restrict__ ad,
                                                     float* __restrict__ out) {
    const int F = 64;
    const int stride = 2 * F;
    int w = blockIdx.x * 8 + (threadIdx.x >> 5);
    if (w >= NN) return;
    int lane = threadIdx.x & 31;
    int fbase = lane * 2;

    float2 acc = make_float2(0.f, 0.f);
    int beg = g_rowptr[w], end = g_rowptr[w + 1];
    int e = beg;
    for (; e + 3 < end; e += 4) {
        int   s0 = g_src[e],   s1 = g_src[e+1], s2 = g_src[e+2], s3 = g_src[e+3];
        float w0 = g_ew[e],    w1 = g_ew[e+1],  w2 = g_ew[e+2],  w3 = g_ew[e+3];
        float2 a0 = *reinterpret_cast<const float2*>(ad + (size_t)s0 * stride + fbase);
        float2 a1 = *reinterpret_cast<const float2*>(ad + (size_t)s1 * stride + fbase);
        float2 a2 = *reinterpret_cast<const float2*>(ad + (size_t)s2 * stride + fbase);
        float2 a3 = *reinterpret_cast<const float2*>(ad + (size_t)s3 * stride + fbase);
        acc.x += w0 * a0.x + w1 * a1.x + w2 * a2.x + w3 * a3.x;
        acc.y += w0 * a0.y + w1 * a1.y + w2 * a2.y + w3 * a3.y;
    }
    for (; e < end; e++) {
        int   s0 = g_src[e];
        float w0 = g_ew[e];
        float2 a0 = *reinterpret_cast<const float2*>(ad + (size_t)s0 * stride + fbase);
        acc.x += w0 * a0.x; acc.y += w0 * a0.y;
    }
    float2 dv = *reinterpret_cast<const float2*>(ad + (size_t)w * stride + F + fbase);
    float v[2];
    v[0] = acc.x + dv.x;
    v[1] = acc.y + dv.y;
    #pragma unroll
    for (int i = 0; i < 2; i++) {
        float t = v[i] > 0.f ? v[i] : 0.1f * v[i];
        v[i] = 1.f / (1.f + expf(-t));
    }
    *reinterpret_cast<float2*>(out + (size_t)w * F + fbase) = make_float2(v[0], v[1]);
}

// ---------------- host launch ----------------
extern "C" void kernel_launch(void* const* d_in, const int* in_sizes, int n_in,
                              void* d_out, int out_size) {
    const float* x  = (const float*)d_in[0];
    const void*  ei = d_in[1];
    const float* ea = (const float*)d_in[2];
    const float* W1_in  = (const float*)d_in[4];
    const float* b1_in  = (const float*)d_in[5];
    const float* W2_in  = (const float*)d_in[6];
    const float* W3_in  = (const float*)d_in[7];
    const float* b3_in  = (const float*)d_in[8];
    const float* W1_mid = (const float*)d_in[9];
    const float* b1_mid = (const float*)d_in[10];
    const float* W2_mid = (const float*)d_in[11];
    const float* W3_mid = (const float*)d_in[12];
    const float* b3_mid = (const float*)d_in[13];
    const float* W1_out = (const float*)d_in[14];
    const float* b1_out = (const float*)d_in[15];
    const float* W2_out = (const float*)d_in[16];
    const float* W3_out = (const float*)d_in[17];
    const float* b3_out = (const float*)d_in[18];

    float* out = (float*)d_out;

    float *d_abc, *d_b0, *d_b1, *d_b2, *d_s;
    __half *d_Ahi, *d_Alo, *d_Wh0, *d_Wl0, *d_Wh1, *d_Wl1, *d_Wh2, *d_Wl2;
    cudaGetSymbolAddress((void**)&d_abc, g_abc);
    cudaGetSymbolAddress((void**)&d_Ahi, g_Ahi);
    cudaGetSymbolAddress((void**)&d_Alo, g_Alo);
    cudaGetSymbolAddress((void**)&d_Wh0, g_Wthi0);
    cudaGetSymbolAddress((void**)&d_Wl0, g_Wtlo0);
    cudaGetSymbolAddress((void**)&d_Wh1, g_Wthi1);
    cudaGetSymbolAddress((void**)&d_Wl1, g_Wtlo1);
    cudaGetSymbolAddress((void**)&d_Wh2, g_Wthi2);
    cudaGetSymbolAddress((void**)&d_Wl2, g_Wtlo2);
    cudaGetSymbolAddress((void**)&d_b0,  g_bcat0);
    cudaGetSymbolAddress((void**)&d_b1,  g_bcat1);
    cudaGetSymbolAddress((void**)&d_b2,  g_bcat2);
    cudaGetSymbolAddress((void**)&d_s,   g_s);

    cudaFuncSetAttribute(tgemm_kernel, cudaFuncAttributeMaxDynamicSharedMemorySize, TG_SMEM);

    // --- one-time stream/event setup (outside capture; no device-memory allocation) ---
    static cudaStream_t s2 = nullptr;
    static cudaEvent_t evStart = nullptr, evPack = nullptr, evHist = nullptr, evCSR = nullptr;
    if (s2 == nullptr) {
        cudaStreamCreateWithFlags(&s2, cudaStreamNonBlocking);
        cudaEventCreateWithFlags(&evStart, cudaEventDisableTiming);
        cudaEventCreateWithFlags(&evPack,  cudaEventDisableTiming);
        cudaEventCreateWithFlags(&evHist,  cudaEventDisableTiming);
        cudaEventCreateWithFlags(&evCSR,   cudaEventDisableTiming);
    }

    // --- fork: side stream does weight packing + x split while main does zero+hist ---
    cudaEventRecord(evStart, 0);
    cudaStreamWaitEvent(s2, evStart, 0);
    pack_w_kernel<<<(F_IN * WID + 255) / 256, 256, 0, s2>>>(W1_in,  b1_in,  W2_in,  W3_in,  b3_in,  F_IN, WID,   d_Wh0, d_Wl0, d_b0);
    pack_w_kernel<<<(WID * WID + 255) / 256, 256, 0, s2>>>(W1_mid, b1_mid, W2_mid, W3_mid, b3_mid, WID,  WID,   d_Wh1, d_Wl1, d_b1);
    pack_w_kernel<<<(WID * F_OUT + 255) / 256, 256, 0, s2>>>(W1_out, b1_out, W2_out, W3_out, b3_out, WID, F_OUT, d_Wh2, d_Wl2, d_b2);
    convert_x_kernel<<<(NN * KK / 4 + 255) / 256, 256, 0, s2>>>((const float4*)x, NN * KK / 4);
    cudaEventRecord(evPack, s2);

    zero_kernel<<<(NN + 255) / 256, 256>>>((const int*)ei);
    hist_kernel<<<(EE + 255) / 256, 256>>>(ei, ea);
    cudaEventRecord(evHist, 0);

    // side stream: CSR chain (needs hist) — overlaps with layer-0 GEMM on main
    cudaStreamWaitEvent(s2, evHist, 0);
    scan1_kernel<<<SCAN_NB, SCAN_B, 0, s2>>>();
    scan3_kernel<<<SCAN_NB, SCAN_B, 0, s2>>>();
    scatter_kernel<<<(EE + 255) / 256, 256, 0, s2>>>(ei, ea);
    cudaEventRecord(evCSR, s2);

    const int spmm_blocks = (NN + 7) / 8;
    const int grid_m = (NN + 127) / 128;

    // --- layer 0 (in) ---
    cudaStreamWaitEvent(0, evPack, 0);
    {
        dim3 grid(grid_m, (3 * WID + 127) / 128);
        tgemm_kernel<<<grid, 256, TG_SMEM>>>(d_Ahi, d_Alo, d_Wh0, d_Wl0, d_b0, d_s, NN, WID, d_abc);
    }
    cudaStreamWaitEvent(0, evCSR, 0);   // join CSR branch before first SpMM
    spmm128_kernel<<<spmm_blocks, 256>>>(d_abc, d_Ahi, d_Alo);

    // --- layers 1,2 (mid) ---
    for (int l = 0; l < 2; l++) {
        dim3 grid(grid_m, (3 * WID + 127) / 128);
        tgemm_kernel<<<grid, 256, TG_SMEM>>>(d_Ahi, d_Alo, d_Wh1, d_Wl1, d_b1, d_s, NN, WID, d_abc);
        spmm128_kernel<<<spmm_blocks, 256>>>(d_abc, d_Ahi, d_Alo);
    }

    // --- layer 3 (out): lrelu+sigmoid, fp32 out ---
    {
        dim3 grid(grid_m, (3 * F_OUT + 127) / 128);
        tgemm_kernel<<<grid, 256, TG_SMEM>>>(d_Ahi, d_Alo, d_Wh2, d_Wl2, d_b2, d_s, NN, F_OUT, d_abc);
        spmm64_kernel<<<spmm_blocks, 256>>>(d_abc, out);
    }
}